// round 6
// baseline (speedup 1.0000x reference)
#include <cuda_runtime.h>
#include <cuda_bf16.h>
#include <math.h>

#define Wd 256
#define Hd 256
#define HW 65536

// ---------------- scratch buffers (no allocation allowed) ----------------
__device__ float g_buf_a[216 * HW];
__device__ float g_buf_b[216 * HW];
__device__ float g_off [144 * HW];
__device__ float g_mask[ 72 * HW];
__device__ float g_cat [128 * HW];

// ---------------- cp.async helpers ----------------
__device__ __forceinline__ unsigned smem_u32(const void* p) {
    return (unsigned)__cvta_generic_to_shared(p);
}
__device__ __forceinline__ void cp_async4(void* dst, const void* src, int src_bytes) {
    asm volatile("cp.async.ca.shared.global [%0], [%1], 4, %2;\n"
                 :: "r"(smem_u32(dst)), "l"(src), "r"(src_bytes) : "memory");
}
__device__ __forceinline__ void cp_commit() {
    asm volatile("cp.async.commit_group;\n" ::: "memory");
}
template<int N>
__device__ __forceinline__ void cp_wait() {
    asm volatile("cp.async.wait_group %0;\n" :: "n"(N) : "memory");
}

// ---------------- generic 3x3 conv, pad=1, stride=1 ----------------
// Block (32,8) = 256 threads. Spatial tile 32 wide x 64 tall (8 rows/thread).
// OCB output channels per block (blockIdx.z). Double-buffered cp.async.
// MODE: 0 = leaky-relu, 1 = plain, 2 = fused offset/mask transform
//   (MODE 2: oc<144 -> out = 10*tanh(v)+flow ; oc>=144 -> out2 = sigmoid(v))
#define TILE_E (66 * 34)   // 2244 smem elements per buffer
template<int CIN, int OCB, int MODE>
__global__ __launch_bounds__(256)
void conv3x3_kernel(const float* __restrict__ in, const float* __restrict__ wt,
                    const float* __restrict__ bias, float* __restrict__ out,
                    const float* __restrict__ flow, float* __restrict__ out2)
{
    __shared__ float sin_[2][TILE_E];
    __shared__ float sw[2][OCB * 9];
    const int tx = threadIdx.x, ty = threadIdx.y;
    const int tid = ty * 32 + tx;
    const int w0 = blockIdx.x * 32;
    const int h0 = blockIdx.y * 64;
    const int ocbase = blockIdx.z * OCB;

    // precompute tile-load offsets once (hoisted out of cin loop)
    int ofs[9];
    unsigned vmask = 0;
#pragma unroll
    for (int it = 0; it < 9; it++) {
        int idx = tid + it * 256;
        ofs[it] = 0;
        if (idx < TILE_E) {
            int r = idx / 34, c = idx - r * 34;
            int gh = h0 + r - 1, gw = w0 + c - 1;
            if ((unsigned)gh < Hd && (unsigned)gw < Wd) {
                ofs[it] = gh * Wd + gw;
                vmask |= 1u << it;
            }
        }
    }
    const int wtid_o = tid / 9, wtid_k = tid - wtid_o * 9;  // for weight loads

    float acc[OCB][8];
#pragma unroll
    for (int o = 0; o < OCB; o++)
#pragma unroll
        for (int i = 0; i < 8; i++) acc[o][i] = 0.f;

    auto issue_loads = [&](int cin, int buf) {
        const float* plane = in + (size_t)cin * HW;
#pragma unroll
        for (int it = 0; it < 9; it++) {
            int idx = tid + it * 256;
            if (idx < TILE_E)
                cp_async4(&sin_[buf][idx], plane + ofs[it],
                          (vmask >> it) & 1 ? 4 : 0);
        }
        if (tid < OCB * 9)
            cp_async4(&sw[buf][tid],
                      &wt[(((size_t)(ocbase + wtid_o)) * CIN + cin) * 9 + wtid_k], 4);
    };

    issue_loads(0, 0);
    cp_commit();

    const int rbase = ty * 8;
    for (int cin = 0; cin < CIN; cin++) {
        const int buf = cin & 1;
        if (cin + 1 < CIN) {
            issue_loads(cin + 1, buf ^ 1);
            cp_commit();
            cp_wait<1>();
        } else {
            cp_wait<0>();
        }
        __syncthreads();

        float v[10][3];
#pragma unroll
        for (int r = 0; r < 10; r++)
#pragma unroll
            for (int c = 0; c < 3; c++)
                v[r][c] = sin_[buf][(rbase + r) * 34 + tx + c];

#pragma unroll
        for (int o = 0; o < OCB; o++) {
            float k00 = sw[buf][o*9+0], k01 = sw[buf][o*9+1], k02 = sw[buf][o*9+2];
            float k10 = sw[buf][o*9+3], k11 = sw[buf][o*9+4], k12 = sw[buf][o*9+5];
            float k20 = sw[buf][o*9+6], k21 = sw[buf][o*9+7], k22 = sw[buf][o*9+8];
#pragma unroll
            for (int i = 0; i < 8; i++) {
                acc[o][i] += k00*v[i  ][0] + k01*v[i  ][1] + k02*v[i  ][2]
                           + k10*v[i+1][0] + k11*v[i+1][1] + k12*v[i+1][2]
                           + k20*v[i+2][0] + k21*v[i+2][1] + k22*v[i+2][2];
            }
        }
        __syncthreads();
    }

#pragma unroll
    for (int o = 0; o < OCB; o++) {
        const int oc = ocbase + o;
        float bv = bias[oc];
#pragma unroll
        for (int i = 0; i < 8; i++) {
            float r = acc[o][i] + bv;
            const int row = h0 + rbase + i;
            const int pix = row * Wd + (w0 + tx);
            if (MODE == 0) {
                r = (r >= 0.f) ? r : 0.1f * r;
                out[(size_t)oc * HW + pix] = r;
            } else if (MODE == 1) {
                out[(size_t)oc * HW + pix] = r;
            } else {
                if (oc < 144) {
                    float f = flow[((oc & 1) ^ 1) * HW + pix];
                    out[(size_t)oc * HW + pix] = 10.0f * tanhf(r) + f;
                } else {
                    out2[(size_t)(oc - 144) * HW + pix] = 1.0f / (1.0f + expf(-r));
                }
            }
        }
    }
}

// ---------------- modulated deformable conv (scalar 8oc x 8px tile) ----------------
__global__ __launch_bounds__(128)
void mdcn_kernel(const float* __restrict__ x, const float* __restrict__ off,
                 const float* __restrict__ mask, const float* __restrict__ wt,
                 const float* __restrict__ bias, float* __restrict__ out)
{
    __shared__ float samp[72 * 128];
    __shared__ float wsm[64 * 73];     // padded stride 73 -> no bank conflict
    const int tid = threadIdx.x;
    const int h = blockIdx.y;
    const int col0 = blockIdx.x * 128;
    const int pix = col0 + tid;        // sampling pixel for this thread
    const int hw = h * Wd + pix;
    const int ob = (tid >> 4) * 8;     // 8 output channels per thread
    const int p0 = (tid & 15) * 8;     // 8 pixels per thread

    float acc[8][8];
#pragma unroll
    for (int o = 0; o < 8; o++)
#pragma unroll
        for (int p = 0; p < 8; p++) acc[o][p] = 0.f;

    for (int g = 0; g < 8; g++) {
        // ---- weight slice for this group: wsm[o][ck], ck = c*9+k ----
        for (int i = tid; i < 64 * 72; i += 128) {
            int o = i / 72, ck = i - o * 72;
            int c = ck / 9, k = ck - c * 9;
            wsm[o * 73 + ck] = wt[((size_t)o * 64 + g * 8 + c) * 9 + k];
        }
        // ---- sampling phase: one pixel per thread, 9 taps x 8 channels ----
#pragma unroll
        for (int k = 0; k < 9; k++) {
            int gk = g * 9 + k;
            float offy = off[(gk * 2 + 0) * HW + hw];
            float offx = off[(gk * 2 + 1) * HW + hw];
            float m    = mask[gk * HW + hw];
            float py = (float)h   + (float)(k / 3 - 1) + offy;
            float px = (float)pix + (float)(k % 3 - 1) + offx;
            float y0f = floorf(py), x0f = floorf(px);
            float ly = py - y0f, lx = px - x0f;
            int y0 = (int)y0f, x0i = (int)x0f;
            int y1 = y0 + 1,  x1 = x0i + 1;
            bool vy0 = (unsigned)y0 < Hd, vy1 = (unsigned)y1 < Hd;
            bool vx0 = (unsigned)x0i < Wd, vx1 = (unsigned)x1 < Wd;
            int yc0 = min(max(y0, 0), Hd - 1), yc1 = min(max(y1, 0), Hd - 1);
            int xc0 = min(max(x0i, 0), Wd - 1), xc1 = min(max(x1, 0), Wd - 1);
            float w00 = (vy0 && vx0) ? (1.f - ly) * (1.f - lx) * m : 0.f;
            float w01 = (vy0 && vx1) ? (1.f - ly) * lx * m : 0.f;
            float w10 = (vy1 && vx0) ? ly * (1.f - lx) * m : 0.f;
            float w11 = (vy1 && vx1) ? ly * lx * m : 0.f;
            int i00 = yc0 * Wd + xc0, i01 = yc0 * Wd + xc1;
            int i10 = yc1 * Wd + xc0, i11 = yc1 * Wd + xc1;
#pragma unroll
            for (int c = 0; c < 8; c++) {
                const float* p = x + (size_t)(g * 8 + c) * HW;
                samp[(c * 9 + k) * 128 + tid] =
                    w00 * p[i00] + w01 * p[i01] + w10 * p[i10] + w11 * p[i11];
            }
        }
        __syncthreads();
        // ---- GEMM: acc[o][p] += W[ob+o, ck] * samp[ck, p0+p] ----
#pragma unroll 2
        for (int ck = 0; ck < 72; ck++) {
            float4 sA = *(const float4*)&samp[ck * 128 + p0];
            float4 sB = *(const float4*)&samp[ck * 128 + p0 + 4];
#pragma unroll
            for (int oi = 0; oi < 8; oi++) {
                float w = wsm[(ob + oi) * 73 + ck];
                acc[oi][0] += w * sA.x;  acc[oi][1] += w * sA.y;
                acc[oi][2] += w * sA.z;  acc[oi][3] += w * sA.w;
                acc[oi][4] += w * sB.x;  acc[oi][5] += w * sB.y;
                acc[oi][6] += w * sB.z;  acc[oi][7] += w * sB.w;
            }
        }
        __syncthreads();
    }

    // ---- epilogue: bias + store (float4 pairs per oc) ----
#pragma unroll
    for (int oi = 0; oi < 8; oi++) {
        float bv = bias[ob + oi];
        float* orow = out + (size_t)(ob + oi) * HW + h * Wd + col0 + p0;
        float4 r0 = make_float4(acc[oi][0] + bv, acc[oi][1] + bv,
                                acc[oi][2] + bv, acc[oi][3] + bv);
        float4 r1 = make_float4(acc[oi][4] + bv, acc[oi][5] + bv,
                                acc[oi][6] + bv, acc[oi][7] + bv);
        *(float4*)(orow)     = r0;
        *(float4*)(orow + 4) = r1;
    }
}

// ---------------- host orchestration ----------------
extern "C" void kernel_launch(void* const* d_in, const int* in_sizes, int n_in,
                              void* d_out, int out_size)
{
    const float* feat_prev       = (const float*)d_in[0];
    const float* feat_next       = (const float*)d_in[1];
    const float* extra_feat_prev = (const float*)d_in[2];
    const float* extra_feat_next = (const float*)d_in[3];
    const float* flow_prev       = (const float*)d_in[4];
    const float* flow_next       = (const float*)d_in[5];
    const float* off1_w[4] = {(const float*)d_in[6],  (const float*)d_in[8],
                              (const float*)d_in[10], (const float*)d_in[12]};
    const float* off1_b[4] = {(const float*)d_in[7],  (const float*)d_in[9],
                              (const float*)d_in[11], (const float*)d_in[13]};
    const float* off2_w[4] = {(const float*)d_in[14], (const float*)d_in[16],
                              (const float*)d_in[18], (const float*)d_in[20]};
    const float* off2_b[4] = {(const float*)d_in[15], (const float*)d_in[17],
                              (const float*)d_in[19], (const float*)d_in[21]};
    const float* dcn1_w = (const float*)d_in[22];
    const float* dcn1_b = (const float*)d_in[23];
    const float* dcn2_w = (const float*)d_in[24];
    const float* dcn2_b = (const float*)d_in[25];
    const float* fus_w  = (const float*)d_in[26];
    const float* fus_b  = (const float*)d_in[27];
    float* out = (float*)d_out;

    float *buf_a, *buf_b, *offp, *maskp, *catp;
    cudaGetSymbolAddress((void**)&buf_a, g_buf_a);
    cudaGetSymbolAddress((void**)&buf_b, g_buf_b);
    cudaGetSymbolAddress((void**)&offp,  g_off);
    cudaGetSymbolAddress((void**)&maskp, g_mask);
    cudaGetSymbolAddress((void**)&catp,  g_cat);

    dim3 cb(32, 8);
    dim3 cg64(8, 4, 8);    // 64 output channels, OCB=8, tile 32x64
    dim3 cg216(8, 4, 27);  // 216 output channels, OCB=8
    dim3 mg(2, 256);       // mdcn: 2 x 128 pixels per row, 256 rows

    // ---- branch prev ----
    conv3x3_kernel<128, 8, 0><<<cg64,  cb>>>(extra_feat_prev, off1_w[0], off1_b[0], buf_a, nullptr, nullptr);
    conv3x3_kernel< 64, 8, 0><<<cg64,  cb>>>(buf_a, off1_w[1], off1_b[1], buf_b, nullptr, nullptr);
    conv3x3_kernel< 64, 8, 0><<<cg64,  cb>>>(buf_b, off1_w[2], off1_b[2], buf_a, nullptr, nullptr);
    conv3x3_kernel< 64, 8, 2><<<cg216, cb>>>(buf_a, off1_w[3], off1_b[3], offp, flow_prev, maskp);
    mdcn_kernel<<<mg, 128>>>(feat_prev, offp, maskp, dcn1_w, dcn1_b, catp);

    // ---- branch next ----
    conv3x3_kernel<128, 8, 0><<<cg64,  cb>>>(extra_feat_next, off2_w[0], off2_b[0], buf_a, nullptr, nullptr);
    conv3x3_kernel< 64, 8, 0><<<cg64,  cb>>>(buf_a, off2_w[1], off2_b[1], buf_b, nullptr, nullptr);
    conv3x3_kernel< 64, 8, 0><<<cg64,  cb>>>(buf_b, off2_w[2], off2_b[2], buf_a, nullptr, nullptr);
    conv3x3_kernel< 64, 8, 2><<<cg216, cb>>>(buf_a, off2_w[3], off2_b[3], offp, flow_next, maskp);
    mdcn_kernel<<<mg, 128>>>(feat_next, offp, maskp, dcn2_w, dcn2_b, catp + (size_t)64 * HW);

    // ---- fusion conv ----
    conv3x3_kernel<128, 8, 1><<<cg64, cb>>>(catp, fus_w, fus_b, out, nullptr, nullptr);
}

// round 8
// speedup vs baseline: 2.6639x; 2.6639x over previous
#include <cuda_runtime.h>
#include <cuda_fp16.h>
#include <math.h>

#define Wd 256
#define Hd 256
#define HW 65536
typedef unsigned int u32;

// ---------------- scratch (no allocation allowed) ----------------
__device__ float g_buf_a[64 * HW];
__device__ float g_buf_b[64 * HW];
__device__ float g_off [144 * HW];
__device__ float g_mask[ 72 * HW];
__device__ float g_cat [128 * HW];
__device__ __half g_whi[663552];
__device__ __half g_wlo[663552];

// ---------------- weight pre-convert: fp32 [OC][CIN][9] -> fp16 hi/lo [9][OCpad][CIN] ----------------
__global__ void wprep_kernel(const float* __restrict__ src, __half* __restrict__ dhi,
                             __half* __restrict__ dlo, int OC, int OCpad, int CIN)
{
    int idx = blockIdx.x * 256 + threadIdx.x;
    int per_t = OCpad * CIN;
    if (idx >= 9 * per_t) return;
    int t = idx / per_t, r = idx - t * per_t;
    int o = r / CIN, c = r - o * CIN;
    float w = (o < OC) ? src[(o * CIN + c) * 9 + t] : 0.f;
    __half h = __float2half_rn(w);
    dhi[idx] = h;
    dlo[idx] = __float2half_rn(w - __half2float(h));
}

__device__ __forceinline__ void mma16816(float* d, const u32* a, u32 b0, u32 b1) {
    asm volatile(
        "mma.sync.aligned.m16n8k16.row.col.f32.f16.f16.f32 "
        "{%0,%1,%2,%3}, {%4,%5,%6,%7}, {%8,%9}, {%0,%1,%2,%3};"
        : "+f"(d[0]), "+f"(d[1]), "+f"(d[2]), "+f"(d[3])
        : "r"(a[0]), "r"(a[1]), "r"(a[2]), "r"(a[3]), "r"(b0), "r"(b1));
}

// ---------------- HMMA implicit-GEMM 3x3 conv ----------------
// CTA: 256 thr (8 warps). Tile: 4 rows x 32 px (M=128) x 64 oc.
// Strip: 6 rows x 34 px x 32 ch fp16 hi/lo in smem; K split in two 32-ch halves.
// MODE: 0 lrelu, 1 plain, 2 offset/mask transform (oc<144 tanh+flow, 144..215 sigmoid).
template<int NCB, int MODE>
__global__ __launch_bounds__(256)
void gconv_kernel(const float* __restrict__ in, const __half* __restrict__ whi,
                  const __half* __restrict__ wlo, const float* __restrict__ bias,
                  int oc_total, int OCpad,
                  float* __restrict__ outf, float* __restrict__ outf2,
                  const float* __restrict__ flow)
{
    __shared__ __half sAhi[204 * 34], sAlo[204 * 34];
    __shared__ __half sWhi[64 * 40], sWlo[64 * 40];
    __shared__ float sbias[64];

    const int tid = threadIdx.x;
    const int wid = tid >> 5, lane = tid & 31;
    const int h0 = (blockIdx.x >> 3) * 4;
    const int w00 = (blockIdx.x & 7) * 32;
    const int ocb = blockIdx.y * 64;
    const int CIN = NCB * 64;

    if (tid < 64) sbias[tid] = (ocb + tid < oc_total) ? bias[ocb + tid] : 0.f;

    float acc[8][4];
#pragma unroll
    for (int i = 0; i < 8; i++)
#pragma unroll
        for (int j = 0; j < 4; j++) acc[i][j] = 0.f;

    for (int cb = 0; cb < NCB; cb++)
    for (int hf = 0; hf < 2; hf++) {
        const int c0 = cb * 64 + hf * 32;
        __syncthreads();                 // protect sA from previous readers
        // ---- stage strip: aligned interior (s = 1..32, float4 over s) ----
#pragma unroll
        for (int i = 0; i < 3; i++) {
            int j = tid + i * 256;       // 768 jobs: 6 rows x 16 cpairs x 8 quads
            int rr = j >> 7, rem = j & 127;
            int cp = rem >> 3, q = rem & 7;
            int gh = h0 - 1 + rr;
            int c = cp * 2;
            float4 va = make_float4(0.f, 0.f, 0.f, 0.f), vb = va;
            if ((unsigned)gh < Hd) {
                const float* p = in + (size_t)(c0 + c) * HW + gh * Wd + (w00 + q * 4);
                va = *(const float4*)p;
                vb = *(const float4*)(p + HW);
            }
            float av[4] = {va.x, va.y, va.z, va.w};
            float bv[4] = {vb.x, vb.y, vb.z, vb.w};
            int ptb = rr * 34 + 1 + q * 4;
#pragma unroll
            for (int k = 0; k < 4; k++) {
                __half ha = __float2half_rn(av[k]), hb = __float2half_rn(bv[k]);
                __half la = __float2half_rn(av[k] - __half2float(ha));
                __half lb = __float2half_rn(bv[k] - __half2float(hb));
                *(__half2*)&sAhi[(ptb + k) * 34 + c] = __halves2half2(ha, hb);
                *(__half2*)&sAlo[(ptb + k) * 34 + c] = __halves2half2(la, lb);
            }
        }
        // ---- edges s=0 and s=33 ----
        if (tid < 192) {
            int rr = tid / 32, rem = tid & 31;
            int cp = rem >> 1, e = rem & 1;
            int s = e ? 33 : 0;
            int gh = h0 - 1 + rr, gw = w00 - 1 + s;
            int c = cp * 2;
            float v0 = 0.f, v1 = 0.f;
            if ((unsigned)gh < Hd && (unsigned)gw < Wd) {
                const float* p = in + (size_t)(c0 + c) * HW + gh * Wd + gw;
                v0 = p[0]; v1 = p[HW];
            }
            __half h0v = __float2half_rn(v0), h1v = __float2half_rn(v1);
            __half l0v = __float2half_rn(v0 - __half2float(h0v));
            __half l1v = __float2half_rn(v1 - __half2float(h1v));
            int pt = rr * 34 + s;
            *(__half2*)&sAhi[pt * 34 + c] = __halves2half2(h0v, h1v);
            *(__half2*)&sAlo[pt * 34 + c] = __halves2half2(l0v, l1v);
        }

        for (int tap = 0; tap < 9; tap++) {
            __syncthreads();             // strip ready / previous tap's sW reads done
            {   // ---- stage W slice [64 oc][32 c] from prepped hi/lo ----
                int o = tid >> 2, q = (tid & 3) * 8;
                size_t gi = (size_t)(tap * OCpad + ocb + o) * CIN + c0 + q;
                *(uint4*)&sWhi[o * 40 + q] = *(const uint4*)&whi[gi];
                *(uint4*)&sWlo[o * 40 + q] = *(const uint4*)&wlo[gi];
            }
            __syncthreads();
            // pixel p = wid*16 + lane/4 (+8); row = p/32 = wid>>1, col = p%32
            const int pt0 = (tap / 3 + (wid >> 1)) * 34 + (tap % 3)
                          + (wid & 1) * 16 + (lane >> 2);
#pragma unroll
            for (int ks = 0; ks < 2; ks++) {
                const int kc = ks * 16 + (lane & 3) * 2;
                u32 ah[4], al[4];
                ah[0] = *(const u32*)&sAhi[pt0 * 34 + kc];
                ah[1] = *(const u32*)&sAhi[(pt0 + 8) * 34 + kc];
                ah[2] = *(const u32*)&sAhi[pt0 * 34 + kc + 8];
                ah[3] = *(const u32*)&sAhi[(pt0 + 8) * 34 + kc + 8];
                al[0] = *(const u32*)&sAlo[pt0 * 34 + kc];
                al[1] = *(const u32*)&sAlo[(pt0 + 8) * 34 + kc];
                al[2] = *(const u32*)&sAlo[pt0 * 34 + kc + 8];
                al[3] = *(const u32*)&sAlo[(pt0 + 8) * 34 + kc + 8];
#pragma unroll
                for (int nf = 0; nf < 8; nf++) {
                    const int n = nf * 8 + (lane >> 2);
                    u32 bh0 = *(const u32*)&sWhi[n * 40 + kc];
                    u32 bh1 = *(const u32*)&sWhi[n * 40 + kc + 8];
                    u32 bl0 = *(const u32*)&sWlo[n * 40 + kc];
                    u32 bl1 = *(const u32*)&sWlo[n * 40 + kc + 8];
                    mma16816(acc[nf], ah, bh0, bh1);
                    mma16816(acc[nf], al, bh0, bh1);
                    mma16816(acc[nf], ah, bl0, bl1);
                }
            }
        }
    }

    // ---- epilogue ----
    const int orow = h0 + (wid >> 1);
    const int pcol = w00 + (wid & 1) * 16 + (lane >> 2);
    const int pix0 = orow * Wd + pcol;        // rows c0,c1
    const int pix1 = pix0 + 8;                // rows c2,c3 (pixel +8)
    const int ocl = (lane & 3) * 2;
#pragma unroll
    for (int nf = 0; nf < 8; nf++) {
        const int oc = ocb + nf * 8 + ocl;
        const float b0 = sbias[nf * 8 + ocl], b1 = sbias[nf * 8 + ocl + 1];
        float v[4] = {acc[nf][0] + b0, acc[nf][1] + b1,
                      acc[nf][2] + b0, acc[nf][3] + b1};
        const int ocs[4] = {oc, oc + 1, oc, oc + 1};
        const int pxs[4] = {pix0, pix0, pix1, pix1};
#pragma unroll
        for (int t = 0; t < 4; t++) {
            float r = v[t];
            const int o2 = ocs[t], px = pxs[t];
            if (MODE == 0) {
                outf[(size_t)o2 * HW + px] = (r >= 0.f) ? r : 0.1f * r;
            } else if (MODE == 1) {
                outf[(size_t)o2 * HW + px] = r;
            } else {
                if (o2 < 144) {
                    outf[(size_t)o2 * HW + px] =
                        10.0f * tanhf(r) + flow[((size_t)((o2 & 1) ^ 1)) * HW + px];
                } else if (o2 < 216) {
                    outf2[(size_t)(o2 - 144) * HW + px] = 1.0f / (1.0f + expf(-r));
                }
            }
        }
    }
}

// ---------------- modulated deformable conv (unchanged, proven) ----------------
__global__ __launch_bounds__(128)
void mdcn_kernel(const float* __restrict__ x, const float* __restrict__ off,
                 const float* __restrict__ mask, const float* __restrict__ wt,
                 const float* __restrict__ bias, float* __restrict__ out)
{
    __shared__ float samp[72 * 128];
    __shared__ float wsm[64 * 73];
    const int tid = threadIdx.x;
    const int h = blockIdx.y;
    const int col0 = blockIdx.x * 128;
    const int pix = col0 + tid;
    const int hw = h * Wd + pix;
    const int ob = (tid >> 4) * 8;
    const int p0 = (tid & 15) * 8;

    float acc[8][8];
#pragma unroll
    for (int o = 0; o < 8; o++)
#pragma unroll
        for (int p = 0; p < 8; p++) acc[o][p] = 0.f;

    for (int g = 0; g < 8; g++) {
        for (int i = tid; i < 64 * 72; i += 128) {
            int o = i / 72, ck = i - o * 72;
            int c = ck / 9, k = ck - c * 9;
            wsm[o * 73 + ck] = wt[((size_t)o * 64 + g * 8 + c) * 9 + k];
        }
#pragma unroll
        for (int k = 0; k < 9; k++) {
            int gk = g * 9 + k;
            float offy = off[(gk * 2 + 0) * HW + hw];
            float offx = off[(gk * 2 + 1) * HW + hw];
            float m    = mask[gk * HW + hw];
            float py = (float)h   + (float)(k / 3 - 1) + offy;
            float px = (float)pix + (float)(k % 3 - 1) + offx;
            float y0f = floorf(py), x0f = floorf(px);
            float ly = py - y0f, lx = px - x0f;
            int y0 = (int)y0f, x0i = (int)x0f;
            int y1 = y0 + 1,  x1 = x0i + 1;
            bool vy0 = (unsigned)y0 < Hd, vy1 = (unsigned)y1 < Hd;
            bool vx0 = (unsigned)x0i < Wd, vx1 = (unsigned)x1 < Wd;
            int yc0 = min(max(y0, 0), Hd - 1), yc1 = min(max(y1, 0), Hd - 1);
            int xc0 = min(max(x0i, 0), Wd - 1), xc1 = min(max(x1, 0), Wd - 1);
            float w00 = (vy0 && vx0) ? (1.f - ly) * (1.f - lx) * m : 0.f;
            float w01 = (vy0 && vx1) ? (1.f - ly) * lx * m : 0.f;
            float w10 = (vy1 && vx0) ? ly * (1.f - lx) * m : 0.f;
            float w11 = (vy1 && vx1) ? ly * lx * m : 0.f;
            int i00 = yc0 * Wd + xc0, i01 = yc0 * Wd + xc1;
            int i10 = yc1 * Wd + xc0, i11 = yc1 * Wd + xc1;
#pragma unroll
            for (int c = 0; c < 8; c++) {
                const float* p = x + (size_t)(g * 8 + c) * HW;
                samp[(c * 9 + k) * 128 + tid] =
                    w00 * p[i00] + w01 * p[i01] + w10 * p[i10] + w11 * p[i11];
            }
        }
        __syncthreads();
#pragma unroll 2
        for (int ck = 0; ck < 72; ck++) {
            float4 sA = *(const float4*)&samp[ck * 128 + p0];
            float4 sB = *(const float4*)&samp[ck * 128 + p0 + 4];
#pragma unroll
            for (int oi = 0; oi < 8; oi++) {
                float w = wsm[(ob + oi) * 73 + ck];
                acc[oi][0] += w * sA.x;  acc[oi][1] += w * sA.y;
                acc[oi][2] += w * sA.z;  acc[oi][3] += w * sA.w;
                acc[oi][4] += w * sB.x;  acc[oi][5] += w * sB.y;
                acc[oi][6] += w * sB.z;  acc[oi][7] += w * sB.w;
            }
        }
        __syncthreads();
    }
#pragma unroll
    for (int oi = 0; oi < 8; oi++) {
        float bv = bias[ob + oi];
        float* orow = out + (size_t)(ob + oi) * HW + h * Wd + col0 + p0;
        *(float4*)(orow)     = make_float4(acc[oi][0]+bv, acc[oi][1]+bv, acc[oi][2]+bv, acc[oi][3]+bv);
        *(float4*)(orow + 4) = make_float4(acc[oi][4]+bv, acc[oi][5]+bv, acc[oi][6]+bv, acc[oi][7]+bv);
    }
}

// ---------------- host orchestration ----------------
extern "C" void kernel_launch(void* const* d_in, const int* in_sizes, int n_in,
                              void* d_out, int out_size)
{
    const float* feat_prev       = (const float*)d_in[0];
    const float* feat_next       = (const float*)d_in[1];
    const float* extra_feat_prev = (const float*)d_in[2];
    const float* extra_feat_next = (const float*)d_in[3];
    const float* flow_prev       = (const float*)d_in[4];
    const float* flow_next       = (const float*)d_in[5];
    const float* o1w[4] = {(const float*)d_in[6],  (const float*)d_in[8],
                           (const float*)d_in[10], (const float*)d_in[12]};
    const float* o1b[4] = {(const float*)d_in[7],  (const float*)d_in[9],
                           (const float*)d_in[11], (const float*)d_in[13]};
    const float* o2w[4] = {(const float*)d_in[14], (const float*)d_in[16],
                           (const float*)d_in[18], (const float*)d_in[20]};
    const float* o2b[4] = {(const float*)d_in[15], (const float*)d_in[17],
                           (const float*)d_in[19], (const float*)d_in[21]};
    const float* dcn1_w = (const float*)d_in[22];
    const float* dcn1_b = (const float*)d_in[23];
    const float* dcn2_w = (const float*)d_in[24];
    const float* dcn2_b = (const float*)d_in[25];
    const float* fus_w  = (const float*)d_in[26];
    const float* fus_b  = (const float*)d_in[27];
    float* out = (float*)d_out;

    float *ba, *bb, *offp, *maskp, *catp;
    __half *whi, *wlo;
    cudaGetSymbolAddress((void**)&ba, g_buf_a);
    cudaGetSymbolAddress((void**)&bb, g_buf_b);
    cudaGetSymbolAddress((void**)&offp,  g_off);
    cudaGetSymbolAddress((void**)&maskp, g_mask);
    cudaGetSymbolAddress((void**)&catp,  g_cat);
    cudaGetSymbolAddress((void**)&whi, g_whi);
    cudaGetSymbolAddress((void**)&wlo, g_wlo);

    // prep all conv weights (offsets in halves)
    auto prep = [&](const float* src, int OC, int OCpad, int CIN, int off) {
        int total = 9 * OCpad * CIN;
        wprep_kernel<<<(total + 255) / 256, 256>>>(src, whi + off, wlo + off, OC, OCpad, CIN);
    };
    prep(o1w[0], 64, 64, 128, 0);
    prep(o1w[1], 64, 64, 64, 73728);
    prep(o1w[2], 64, 64, 64, 110592);
    prep(o1w[3], 216, 256, 64, 147456);
    prep(o2w[0], 64, 64, 128, 294912);
    prep(o2w[1], 64, 64, 64, 368640);
    prep(o2w[2], 64, 64, 64, 405504);
    prep(o2w[3], 216, 256, 64, 442368);
    prep(fus_w, 64, 64, 128, 589824);

    dim3 g1(512, 1), g4(512, 4), mg(2, 256);

    gconv_kernel<2,0><<<g1, 256>>>(extra_feat_prev, whi + 0, wlo + 0, o1b[0], 64, 64, ba, nullptr, nullptr);
    gconv_kernel<1,0><<<g1, 256>>>(ba, whi + 73728, wlo + 73728, o1b[1], 64, 64, bb, nullptr, nullptr);
    gconv_kernel<1,0><<<g1, 256>>>(bb, whi + 110592, wlo + 110592, o1b[2], 64, 64, ba, nullptr, nullptr);
    gconv_kernel<1,2><<<g4, 256>>>(ba, whi + 147456, wlo + 147456, o1b[3], 216, 256, offp, maskp, flow_prev);
    mdcn_kernel<<<mg, 128>>>(feat_prev, offp, maskp, dcn1_w, dcn1_b, catp);

    gconv_kernel<2,0><<<g1, 256>>>(extra_feat_next, whi + 294912, wlo + 294912, o2b[0], 64, 64, ba, nullptr, nullptr);
    gconv_kernel<1,0><<<g1, 256>>>(ba, whi + 368640, wlo + 368640, o2b[1], 64, 64, bb, nullptr, nullptr);
    gconv_kernel<1,0><<<g1, 256>>>(bb, whi + 405504, wlo + 405504, o2b[2], 64, 64, ba, nullptr, nullptr);
    gconv_kernel<1,2><<<g4, 256>>>(ba, whi + 442368, wlo + 442368, o2b[3], 216, 256, offp, maskp, flow_next);
    mdcn_kernel<<<mg, 128>>>(feat_next, offp, maskp, dcn2_w, dcn2_b, catp + (size_t)64 * HW);

    gconv_kernel<2,1><<<g1, 256>>>(catp, whi + 589824, wlo + 589824, fus_b, 64, 64, out, nullptr, nullptr);
}

// round 9
// speedup vs baseline: 4.1646x; 1.5633x over previous
#include <cuda_runtime.h>
#include <cuda_fp16.h>
#include <math.h>

#define Wd 256
#define Hd 256
#define HW 65536
typedef unsigned int u32;

// ---------------- scratch (no allocation allowed) ----------------
__device__ float g_buf_a[64 * HW];
__device__ float g_buf_b[64 * HW];
__device__ float g_off [144 * HW];
__device__ float g_mask[ 72 * HW];
__device__ float g_cat [128 * HW];
__device__ float g_xt  [64 * HW];          // NHWC feat
__device__ __align__(16) __half g_whi[663552];
__device__ __align__(16) __half g_wlo[663552];
__device__ __align__(16) __half g_dwhi[2 * 45056];
__device__ __align__(16) __half g_dwlo[2 * 45056];

// ---------------- weight pre-convert (convs) ----------------
__global__ void wprep_kernel(const float* __restrict__ src, __half* __restrict__ dhi,
                             __half* __restrict__ dlo, int OC, int OCpad, int CIN)
{
    int idx = blockIdx.x * 256 + threadIdx.x;
    int per_t = OCpad * CIN;
    if (idx >= 9 * per_t) return;
    int t = idx / per_t, r = idx - t * per_t;
    int o = r / CIN, c = r - o * CIN;
    float w = (o < OC) ? src[(o * CIN + c) * 9 + t] : 0.f;
    __half h = __float2half_rn(w);
    dhi[idx] = h;
    dlo[idx] = __float2half_rn(w - __half2float(h));
}

// ---------------- dcn weight pre-convert: [64][64][9] -> [g=8][o=64][ck=88] hi/lo ----------------
__global__ void dcnprep_kernel(const float* __restrict__ src, __half* __restrict__ dhi,
                               __half* __restrict__ dlo)
{
    int idx = blockIdx.x * 256 + threadIdx.x;
    if (idx >= 45056) return;
    int g = idx / 5632, r = idx - g * 5632, o = r / 88, ck = r - o * 88;
    float w = 0.f;
    if (ck < 72) { int c = ck / 9, k = ck - c * 9; w = src[((size_t)o * 64 + g * 8 + c) * 9 + k]; }
    __half h = __float2half_rn(w);
    dhi[idx] = h;
    dlo[idx] = __float2half_rn(w - __half2float(h));
}

// ---------------- NCHW -> NHWC (fp32) ----------------
__global__ __launch_bounds__(128)
void tohwc_kernel(const float* __restrict__ src, float* __restrict__ dst)
{
    __shared__ float s[64 * 130];
    const int t = threadIdx.x;
    const int pix0 = blockIdx.x * 128;
    for (int c = 0; c < 64; c++) s[c * 130 + t] = src[(size_t)c * HW + pix0 + t];
    __syncthreads();
    for (int i = 0; i < 64; i++) {
        int L = t + i * 128;
        dst[(size_t)pix0 * 64 + L] = s[(L & 63) * 130 + (L >> 6)];
    }
}

__device__ __forceinline__ void mma16816(float* d, const u32* a, u32 b0, u32 b1) {
    asm volatile(
        "mma.sync.aligned.m16n8k16.row.col.f32.f16.f16.f32 "
        "{%0,%1,%2,%3}, {%4,%5,%6,%7}, {%8,%9}, {%0,%1,%2,%3};"
        : "+f"(d[0]), "+f"(d[1]), "+f"(d[2]), "+f"(d[3])
        : "r"(a[0]), "r"(a[1]), "r"(a[2]), "r"(a[3]), "r"(b0), "r"(b1));
}

// ---------------- HMMA implicit-GEMM 3x3 conv (unchanged from R8) ----------------
template<int NCB, int MODE>
__global__ __launch_bounds__(256)
void gconv_kernel(const float* __restrict__ in, const __half* __restrict__ whi,
                  const __half* __restrict__ wlo, const float* __restrict__ bias,
                  int oc_total, int OCpad,
                  float* __restrict__ outf, float* __restrict__ outf2,
                  const float* __restrict__ flow)
{
    __shared__ __half sAhi[204 * 34], sAlo[204 * 34];
    __shared__ __half sWhi[64 * 40], sWlo[64 * 40];
    __shared__ float sbias[64];

    const int tid = threadIdx.x;
    const int wid = tid >> 5, lane = tid & 31;
    const int h0 = (blockIdx.x >> 3) * 4;
    const int w00 = (blockIdx.x & 7) * 32;
    const int ocb = blockIdx.y * 64;
    const int CIN = NCB * 64;

    if (tid < 64) sbias[tid] = (ocb + tid < oc_total) ? bias[ocb + tid] : 0.f;

    float acc[8][4];
#pragma unroll
    for (int i = 0; i < 8; i++)
#pragma unroll
        for (int j = 0; j < 4; j++) acc[i][j] = 0.f;

    for (int cb = 0; cb < NCB; cb++)
    for (int hf = 0; hf < 2; hf++) {
        const int c0 = cb * 64 + hf * 32;
        __syncthreads();
#pragma unroll
        for (int i = 0; i < 3; i++) {
            int j = tid + i * 256;
            int rr = j >> 7, rem = j & 127;
            int cp = rem >> 3, q = rem & 7;
            int gh = h0 - 1 + rr;
            int c = cp * 2;
            float4 va = make_float4(0.f, 0.f, 0.f, 0.f), vb = va;
            if ((unsigned)gh < Hd) {
                const float* p = in + (size_t)(c0 + c) * HW + gh * Wd + (w00 + q * 4);
                va = *(const float4*)p;
                vb = *(const float4*)(p + HW);
            }
            float av[4] = {va.x, va.y, va.z, va.w};
            float bv[4] = {vb.x, vb.y, vb.z, vb.w};
            int ptb = rr * 34 + 1 + q * 4;
#pragma unroll
            for (int k = 0; k < 4; k++) {
                __half ha = __float2half_rn(av[k]), hb = __float2half_rn(bv[k]);
                __half la = __float2half_rn(av[k] - __half2float(ha));
                __half lb = __float2half_rn(bv[k] - __half2float(hb));
                *(__half2*)&sAhi[(ptb + k) * 34 + c] = __halves2half2(ha, hb);
                *(__half2*)&sAlo[(ptb + k) * 34 + c] = __halves2half2(la, lb);
            }
        }
        if (tid < 192) {
            int rr = tid / 32, rem = tid & 31;
            int cp = rem >> 1, e = rem & 1;
            int s = e ? 33 : 0;
            int gh = h0 - 1 + rr, gw = w00 - 1 + s;
            int c = cp * 2;
            float v0 = 0.f, v1 = 0.f;
            if ((unsigned)gh < Hd && (unsigned)gw < Wd) {
                const float* p = in + (size_t)(c0 + c) * HW + gh * Wd + gw;
                v0 = p[0]; v1 = p[HW];
            }
            __half h0v = __float2half_rn(v0), h1v = __float2half_rn(v1);
            __half l0v = __float2half_rn(v0 - __half2float(h0v));
            __half l1v = __float2half_rn(v1 - __half2float(h1v));
            int pt = rr * 34 + s;
            *(__half2*)&sAhi[pt * 34 + c] = __halves2half2(h0v, h1v);
            *(__half2*)&sAlo[pt * 34 + c] = __halves2half2(l0v, l1v);
        }

        for (int tap = 0; tap < 9; tap++) {
            __syncthreads();
            {
                int o = tid >> 2, q = (tid & 3) * 8;
                size_t gi = (size_t)(tap * OCpad + ocb + o) * CIN + c0 + q;
                *(uint4*)&sWhi[o * 40 + q] = *(const uint4*)&whi[gi];
                *(uint4*)&sWlo[o * 40 + q] = *(const uint4*)&wlo[gi];
            }
            __syncthreads();
            const int pt0 = (tap / 3 + (wid >> 1)) * 34 + (tap % 3)
                          + (wid & 1) * 16 + (lane >> 2);
#pragma unroll
            for (int ks = 0; ks < 2; ks++) {
                const int kc = ks * 16 + (lane & 3) * 2;
                u32 ah[4], al[4];
                ah[0] = *(const u32*)&sAhi[pt0 * 34 + kc];
                ah[1] = *(const u32*)&sAhi[(pt0 + 8) * 34 + kc];
                ah[2] = *(const u32*)&sAhi[pt0 * 34 + kc + 8];
                ah[3] = *(const u32*)&sAhi[(pt0 + 8) * 34 + kc + 8];
                al[0] = *(const u32*)&sAlo[pt0 * 34 + kc];
                al[1] = *(const u32*)&sAlo[(pt0 + 8) * 34 + kc];
                al[2] = *(const u32*)&sAlo[pt0 * 34 + kc + 8];
                al[3] = *(const u32*)&sAlo[(pt0 + 8) * 34 + kc + 8];
#pragma unroll
                for (int nf = 0; nf < 8; nf++) {
                    const int n = nf * 8 + (lane >> 2);
                    u32 bh0 = *(const u32*)&sWhi[n * 40 + kc];
                    u32 bh1 = *(const u32*)&sWhi[n * 40 + kc + 8];
                    u32 bl0 = *(const u32*)&sWlo[n * 40 + kc];
                    u32 bl1 = *(const u32*)&sWlo[n * 40 + kc + 8];
                    mma16816(acc[nf], ah, bh0, bh1);
                    mma16816(acc[nf], al, bh0, bh1);
                    mma16816(acc[nf], ah, bl0, bl1);
                }
            }
        }
    }

    const int orow = h0 + (wid >> 1);
    const int pcol = w00 + (wid & 1) * 16 + (lane >> 2);
    const int pix0 = orow * Wd + pcol;
    const int pix1 = pix0 + 8;
    const int ocl = (lane & 3) * 2;
#pragma unroll
    for (int nf = 0; nf < 8; nf++) {
        const int oc = ocb + nf * 8 + ocl;
        const float b0 = sbias[nf * 8 + ocl], b1 = sbias[nf * 8 + ocl + 1];
        float v[4] = {acc[nf][0] + b0, acc[nf][1] + b1,
                      acc[nf][2] + b0, acc[nf][3] + b1};
        const int ocs[4] = {oc, oc + 1, oc, oc + 1};
        const int pxs[4] = {pix0, pix0, pix1, pix1};
#pragma unroll
        for (int t = 0; t < 4; t++) {
            float r = v[t];
            const int o2 = ocs[t], px = pxs[t];
            if (MODE == 0) {
                outf[(size_t)o2 * HW + px] = (r >= 0.f) ? r : 0.1f * r;
            } else if (MODE == 1) {
                outf[(size_t)o2 * HW + px] = r;
            } else {
                if (o2 < 144) {
                    outf[(size_t)o2 * HW + px] =
                        10.0f * tanhf(r) + flow[((size_t)((o2 & 1) ^ 1)) * HW + px];
                } else if (o2 < 216) {
                    outf2[(size_t)(o2 - 144) * HW + px] = 1.0f / (1.0f + expf(-r));
                }
            }
        }
    }
}

// ---------------- mdcn v2: NHWC gather + HMMA GEMM ----------------
// 256 thr (8 warps... 4 warps of MMA rows), 64 pixels per block.
// Sampling: px = tid&63, part = tid>>6 handles taps {0-2 | 3-4 | 5-6 | 7-8}.
// GEMM: 4 warps x m16 = 64 px, N=64 oc, K=80 (72 + zero pad), fp16 hi/lo.
__global__ __launch_bounds__(256)
void mdcn_kernel(const float* __restrict__ xt, const float* __restrict__ off,
                 const float* __restrict__ mask, const __half* __restrict__ dwhi,
                 const __half* __restrict__ dwlo, const float* __restrict__ bias,
                 float* __restrict__ out)
{
    __shared__ __align__(16) __half sShi[64 * 90], sSlo[64 * 90];
    __shared__ __align__(16) __half sWhi[64 * 88], sWlo[64 * 88];
    __shared__ float sbias[64];
    const int tid = threadIdx.x;
    const int wid = tid >> 5, lane = tid & 31;
    const int h = blockIdx.y;
    const int col0 = blockIdx.x * 64;
    const int px = tid & 63;
    const int part = tid >> 6;
    const int pixg = col0 + px;
    const int hw = h * Wd + pixg;
    const int k_beg = (part == 0) ? 0 : 1 + part * 2;
    const int k_end = (part == 0) ? 3 : 3 + part * 2;

    if (tid < 64) sbias[tid] = bias[tid];
    for (int i = tid; i < 64 * 8; i += 256) {
        int p = i >> 3, j = i & 7;
        sShi[p * 90 + 72 + j] = __ushort_as_half(0);
        sSlo[p * 90 + 72 + j] = __ushort_as_half(0);
    }

    float acc[8][4];
#pragma unroll
    for (int i = 0; i < 8; i++)
#pragma unroll
        for (int j = 0; j < 4; j++) acc[i][j] = 0.f;

    for (int g = 0; g < 8; g++) {
        __syncthreads();     // previous GEMM done reading sS/sW
        // stage W slice (group g): 5632 halves hi + lo
        {
            const u32* gh32 = (const u32*)(dwhi + g * 5632);
            const u32* gl32 = (const u32*)(dwlo + g * 5632);
            for (int i = tid; i < 2816; i += 256) {
                ((u32*)sWhi)[i] = gh32[i];
                ((u32*)sWlo)[i] = gl32[i];
            }
        }
        // sampling: this thread's taps
        for (int k = k_beg; k < k_end; k++) {
            int gk = g * 9 + k;
            float offy = off[(gk * 2 + 0) * HW + hw];
            float offx = off[(gk * 2 + 1) * HW + hw];
            float m    = mask[gk * HW + hw];
            float py = (float)h    + (float)(k / 3 - 1) + offy;
            float pxf = (float)pixg + (float)(k % 3 - 1) + offx;
            float y0f = floorf(py), x0f = floorf(pxf);
            float ly = py - y0f, lx = pxf - x0f;
            int y0 = (int)y0f, x0i = (int)x0f;
            int y1 = y0 + 1,  x1 = x0i + 1;
            bool vy0 = (unsigned)y0 < Hd, vy1 = (unsigned)y1 < Hd;
            bool vx0 = (unsigned)x0i < Wd, vx1 = (unsigned)x1 < Wd;
            int yc0 = min(max(y0, 0), Hd - 1), yc1 = min(max(y1, 0), Hd - 1);
            int xc0 = min(max(x0i, 0), Wd - 1), xc1 = min(max(x1, 0), Wd - 1);
            float w00 = (vy0 && vx0) ? (1.f - ly) * (1.f - lx) * m : 0.f;
            float w01 = (vy0 && vx1) ? (1.f - ly) * lx * m : 0.f;
            float w10 = (vy1 && vx0) ? ly * (1.f - lx) * m : 0.f;
            float w11 = (vy1 && vx1) ? ly * lx * m : 0.f;
            const float* b00 = xt + ((size_t)(yc0 * Wd + xc0)) * 64 + g * 8;
            const float* b01 = xt + ((size_t)(yc0 * Wd + xc1)) * 64 + g * 8;
            const float* b10 = xt + ((size_t)(yc1 * Wd + xc0)) * 64 + g * 8;
            const float* b11 = xt + ((size_t)(yc1 * Wd + xc1)) * 64 + g * 8;
            float4 a0 = *(const float4*)b00, a1 = *(const float4*)(b00 + 4);
            float4 c0 = *(const float4*)b01, c1 = *(const float4*)(b01 + 4);
            float4 d0 = *(const float4*)b10, d1 = *(const float4*)(b10 + 4);
            float4 e0 = *(const float4*)b11, e1 = *(const float4*)(b11 + 4);
            float A[8] = {a0.x,a0.y,a0.z,a0.w,a1.x,a1.y,a1.z,a1.w};
            float B[8] = {c0.x,c0.y,c0.z,c0.w,c1.x,c1.y,c1.z,c1.w};
            float C[8] = {d0.x,d0.y,d0.z,d0.w,d1.x,d1.y,d1.z,d1.w};
            float D[8] = {e0.x,e0.y,e0.z,e0.w,e1.x,e1.y,e1.z,e1.w};
#pragma unroll
            for (int c = 0; c < 8; c++) {
                float s = w00 * A[c] + w01 * B[c] + w10 * C[c] + w11 * D[c];
                __half hv = __float2half_rn(s);
                sShi[px * 90 + c * 9 + k] = hv;
                sSlo[px * 90 + c * 9 + k] = __float2half_rn(s - __half2float(hv));
            }
        }
        __syncthreads();
        // GEMM: warps 0-3 own m16 slabs; warps 4-7 duplicate rows of 0-3? No:
        // only 4 m-slabs exist (64 px). Warps 4-7 take nf 4..7, warps 0-3 nf 0..3.
        const int mw = wid & 3;           // m-slab
        const int nhalf = (wid >> 2) * 4; // nf offset: 0 or 4
        const int r = mw * 16 + (lane >> 2);
#pragma unroll
        for (int ks = 0; ks < 5; ks++) {
            const int kc = ks * 16 + (lane & 3) * 2;
            u32 ah[4], al[4];
            ah[0] = *(const u32*)&sShi[r * 90 + kc];
            ah[1] = *(const u32*)&sShi[(r + 8) * 90 + kc];
            ah[2] = *(const u32*)&sShi[r * 90 + kc + 8];
            ah[3] = *(const u32*)&sShi[(r + 8) * 90 + kc + 8];
            al[0] = *(const u32*)&sSlo[r * 90 + kc];
            al[1] = *(const u32*)&sSlo[(r + 8) * 90 + kc];
            al[2] = *(const u32*)&sSlo[r * 90 + kc + 8];
            al[3] = *(const u32*)&sSlo[(r + 8) * 90 + kc + 8];
#pragma unroll
            for (int nf = 0; nf < 4; nf++) {
                const int n = (nhalf + nf) * 8 + (lane >> 2);
                u32 bh0 = *(const u32*)&sWhi[n * 88 + kc];
                u32 bh1 = *(const u32*)&sWhi[n * 88 + kc + 8];
                u32 bl0 = *(const u32*)&sWlo[n * 88 + kc];
                u32 bl1 = *(const u32*)&sWlo[n * 88 + kc + 8];
                mma16816(acc[nf], ah, bh0, bh1);
                mma16816(acc[nf], al, bh0, bh1);
                mma16816(acc[nf], ah, bl0, bl1);
            }
        }
    }
    // epilogue: 4 nf frags per thread (warps 0-3: nf 0-3; 4-7: nf 4-7)
    const int mw = wid & 3, nhalf = (wid >> 2) * 4;
    const int p1 = col0 + mw * 16 + (lane >> 2);
    const int p2 = p1 + 8;
    const int oc0 = (lane & 3) * 2;
#pragma unroll
    for (int nf = 0; nf < 4; nf++) {
        const int oc = (nhalf + nf) * 8 + oc0;
        out[(size_t)oc * HW + h * Wd + p1]       = acc[nf][0] + sbias[oc];
        out[(size_t)(oc + 1) * HW + h * Wd + p1] = acc[nf][1] + sbias[oc + 1];
        out[(size_t)oc * HW + h * Wd + p2]       = acc[nf][2] + sbias[oc];
        out[(size_t)(oc + 1) * HW + h * Wd + p2] = acc[nf][3] + sbias[oc + 1];
    }
}

// ---------------- host orchestration ----------------
extern "C" void kernel_launch(void* const* d_in, const int* in_sizes, int n_in,
                              void* d_out, int out_size)
{
    const float* feat_prev       = (const float*)d_in[0];
    const float* feat_next       = (const float*)d_in[1];
    const float* extra_feat_prev = (const float*)d_in[2];
    const float* extra_feat_next = (const float*)d_in[3];
    const float* flow_prev       = (const float*)d_in[4];
    const float* flow_next       = (const float*)d_in[5];
    const float* o1w[4] = {(const float*)d_in[6],  (const float*)d_in[8],
                           (const float*)d_in[10], (const float*)d_in[12]};
    const float* o1b[4] = {(const float*)d_in[7],  (const float*)d_in[9],
                           (const float*)d_in[11], (const float*)d_in[13]};
    const float* o2w[4] = {(const float*)d_in[14], (const float*)d_in[16],
                           (const float*)d_in[18], (const float*)d_in[20]};
    const float* o2b[4] = {(const float*)d_in[15], (const float*)d_in[17],
                           (const float*)d_in[19], (const float*)d_in[21]};
    const float* dcn1_w = (const float*)d_in[22];
    const float* dcn1_b = (const float*)d_in[23];
    const float* dcn2_w = (const float*)d_in[24];
    const float* dcn2_b = (const float*)d_in[25];
    const float* fus_w  = (const float*)d_in[26];
    const float* fus_b  = (const float*)d_in[27];
    float* out = (float*)d_out;

    float *ba, *bb, *offp, *maskp, *catp, *xt;
    __half *whi, *wlo, *dwhi, *dwlo;
    cudaGetSymbolAddress((void**)&ba, g_buf_a);
    cudaGetSymbolAddress((void**)&bb, g_buf_b);
    cudaGetSymbolAddress((void**)&offp,  g_off);
    cudaGetSymbolAddress((void**)&maskp, g_mask);
    cudaGetSymbolAddress((void**)&catp,  g_cat);
    cudaGetSymbolAddress((void**)&xt,    g_xt);
    cudaGetSymbolAddress((void**)&whi, g_whi);
    cudaGetSymbolAddress((void**)&wlo, g_wlo);
    cudaGetSymbolAddress((void**)&dwhi, g_dwhi);
    cudaGetSymbolAddress((void**)&dwlo, g_dwlo);

    auto prep = [&](const float* src, int OC, int OCpad, int CIN, int off_) {
        int total = 9 * OCpad * CIN;
        wprep_kernel<<<(total + 255) / 256, 256>>>(src, whi + off_, wlo + off_, OC, OCpad, CIN);
    };
    prep(o1w[0], 64, 64, 128, 0);
    prep(o1w[1], 64, 64, 64, 73728);
    prep(o1w[2], 64, 64, 64, 110592);
    prep(o1w[3], 216, 256, 64, 147456);
    prep(o2w[0], 64, 64, 128, 294912);
    prep(o2w[1], 64, 64, 64, 368640);
    prep(o2w[2], 64, 64, 64, 405504);
    prep(o2w[3], 216, 256, 64, 442368);
    prep(fus_w, 64, 64, 128, 589824);
    dcnprep_kernel<<<176, 256>>>(dcn1_w, dwhi, dwlo);
    dcnprep_kernel<<<176, 256>>>(dcn2_w, dwhi + 45056, dwlo + 45056);

    dim3 g1(512, 1), g4(512, 4), mg(4, 256);

    gconv_kernel<2,0><<<g1, 256>>>(extra_feat_prev, whi + 0, wlo + 0, o1b[0], 64, 64, ba, nullptr, nullptr);
    gconv_kernel<1,0><<<g1, 256>>>(ba, whi + 73728, wlo + 73728, o1b[1], 64, 64, bb, nullptr, nullptr);
    gconv_kernel<1,0><<<g1, 256>>>(bb, whi + 110592, wlo + 110592, o1b[2], 64, 64, ba, nullptr, nullptr);
    gconv_kernel<1,2><<<g4, 256>>>(ba, whi + 147456, wlo + 147456, o1b[3], 216, 256, offp, maskp, flow_prev);
    tohwc_kernel<<<512, 128>>>(feat_prev, xt);
    mdcn_kernel<<<mg, 256>>>(xt, offp, maskp, dwhi, dwlo, dcn1_b, catp);

    gconv_kernel<2,0><<<g1, 256>>>(extra_feat_next, whi + 294912, wlo + 294912, o2b[0], 64, 64, ba, nullptr, nullptr);
    gconv_kernel<1,0><<<g1, 256>>>(ba, whi + 368640, wlo + 368640, o2b[1], 64, 64, bb, nullptr, nullptr);
    gconv_kernel<1,0><<<g1, 256>>>(bb, whi + 405504, wlo + 405504, o2b[2], 64, 64, ba, nullptr, nullptr);
    gconv_kernel<1,2><<<g4, 256>>>(ba, whi + 442368, wlo + 442368, o2b[3], 216, 256, offp, maskp, flow_next);
    tohwc_kernel<<<512, 128>>>(feat_next, xt);
    mdcn_kernel<<<mg, 256>>>(xt, offp, maskp, dwhi + 45056, dwlo + 45056, dcn2_b, catp + (size_t)64 * HW);

    gconv_kernel<2,1><<<g1, 256>>>(catp, whi + 589824, wlo + 589824, fus_b, 64, 64, out, nullptr, nullptr);
}

// round 11
// speedup vs baseline: 4.5572x; 1.0943x over previous
#include <cuda_runtime.h>
#include <cuda_fp16.h>
#include <math.h>

#define Wd 256
#define Hd 256
#define HW 65536
typedef unsigned int u32;

// ---------------- scratch (no allocation allowed) ----------------
__device__ float g_buf_a[64 * HW];
__device__ float g_buf_b[64 * HW];
__device__ float g_off [144 * HW];
__device__ float g_mask[ 72 * HW];
__device__ float g_cat [128 * HW];
__device__ __align__(16) __half g_xt[64 * HW];          // NHWC feat, fp16
__device__ __align__(16) __half g_whi[663552];
__device__ __align__(16) __half g_wlo[663552];
__device__ __align__(16) __half g_dwhi[2 * 45056];
__device__ __align__(16) __half g_dwlo[2 * 45056];

// ---------------- merged conv-weight pre-convert ----------------
struct WSrc { const float* p[9]; };
__global__ void wprep_all(WSrc ws, __half* __restrict__ dhi, __half* __restrict__ dlo)
{
    const int off[9]  = {0,73728,110592,147456,294912,368640,405504,442368,589824};
    const int CINs[9] = {128,64,64,64,128,64,64,64,128};
    const int OCs[9]  = {64,64,64,216,64,64,64,216,64};
    const int OCp[9]  = {64,64,64,256,64,64,64,256,64};
    int idx = blockIdx.x * 256 + threadIdx.x;
    if (idx >= 663552) return;
    int seg = 0;
#pragma unroll
    for (int s = 1; s < 9; s++) if (idx >= off[s]) seg = s;
    int r = idx - off[seg];
    int per_t = OCp[seg] * CINs[seg];
    int t = r / per_t; r -= t * per_t;
    int o = r / CINs[seg], c = r - o * CINs[seg];
    float w = (o < OCs[seg]) ? ws.p[seg][(o * CINs[seg] + c) * 9 + t] : 0.f;
    __half h = __float2half_rn(w);
    dhi[idx] = h;
    dlo[idx] = __float2half_rn(w - __half2float(h));
}

// ---------------- dcn weight pre-convert: both branches ----------------
__global__ void dcnprep_all(const float* __restrict__ s1, const float* __restrict__ s2,
                            __half* __restrict__ dhi, __half* __restrict__ dlo)
{
    int idx = blockIdx.x * 256 + threadIdx.x;
    if (idx >= 45056) return;
    const float* src = blockIdx.y ? s2 : s1;
    int base = blockIdx.y * 45056;
    int g = idx / 5632, r = idx - g * 5632, o = r / 88, ck = r - o * 88;
    float w = 0.f;
    if (ck < 72) { int c = ck / 9, k = ck - c * 9; w = src[((size_t)o * 64 + g * 8 + c) * 9 + k]; }
    __half h = __float2half_rn(w);
    dhi[base + idx] = h;
    dlo[base + idx] = __float2half_rn(w - __half2float(h));
}

// ---------------- NCHW fp32 -> NHWC fp16 ----------------
__global__ __launch_bounds__(128)
void tohwc_kernel(const float* __restrict__ src, __half* __restrict__ dst)
{
    __shared__ float s[64 * 130];
    const int t = threadIdx.x;
    const int pix0 = blockIdx.x * 128;
    for (int c = 0; c < 64; c++) s[c * 130 + t] = src[(size_t)c * HW + pix0 + t];
    __syncthreads();
    for (int i = 0; i < 64; i++) {
        int L = t + i * 128;
        dst[(size_t)pix0 * 64 + L] = __float2half_rn(s[(L & 63) * 130 + (L >> 6)]);
    }
}

__device__ __forceinline__ void mma16816(float* d, const u32* a, u32 b0, u32 b1) {
    asm volatile(
        "mma.sync.aligned.m16n8k16.row.col.f32.f16.f16.f32 "
        "{%0,%1,%2,%3}, {%4,%5,%6,%7}, {%8,%9}, {%0,%1,%2,%3};"
        : "+f"(d[0]), "+f"(d[1]), "+f"(d[2]), "+f"(d[3])
        : "r"(a[0]), "r"(a[1]), "r"(a[2]), "r"(a[3]), "r"(b0), "r"(b1));
}

// ---------------- HMMA implicit-GEMM 3x3 conv ----------------
template<int NCB, int MODE>
__global__ __launch_bounds__(256)
void gconv_kernel(const float* __restrict__ in, const __half* __restrict__ whi,
                  const __half* __restrict__ wlo, const float* __restrict__ bias,
                  int oc_total, int OCpad,
                  float* __restrict__ outf, float* __restrict__ outf2,
                  const float* __restrict__ flow)
{
    __shared__ __half sAhi[204 * 34], sAlo[204 * 34];
    __shared__ __half sWhi[64 * 40], sWlo[64 * 40];
    __shared__ float sbias[64];

    const int tid = threadIdx.x;
    const int wid = tid >> 5, lane = tid & 31;
    const int h0 = (blockIdx.x >> 3) * 4;
    const int w00 = (blockIdx.x & 7) * 32;
    const int ocb = blockIdx.y * 64;
    const int CIN = NCB * 64;
    int nfb = (oc_total - ocb + 7) >> 3; if (nfb > 8) nfb = 8;

    if (tid < 64) sbias[tid] = (ocb + tid < oc_total) ? bias[ocb + tid] : 0.f;

    float acc[8][4];
#pragma unroll
    for (int i = 0; i < 8; i++)
#pragma unroll
        for (int j = 0; j < 4; j++) acc[i][j] = 0.f;

    for (int cb = 0; cb < NCB; cb++)
    for (int hf = 0; hf < 2; hf++) {
        const int c0 = cb * 64 + hf * 32;
        __syncthreads();
#pragma unroll
        for (int i = 0; i < 3; i++) {
            int j = tid + i * 256;
            int rr = j >> 7, rem = j & 127;
            int cp = rem >> 3, q = rem & 7;
            int gh = h0 - 1 + rr;
            int c = cp * 2;
            float4 va = make_float4(0.f, 0.f, 0.f, 0.f), vb = va;
            if ((unsigned)gh < Hd) {
                const float* p = in + (size_t)(c0 + c) * HW + gh * Wd + (w00 + q * 4);
                va = *(const float4*)p;
                vb = *(const float4*)(p + HW);
            }
            float av[4] = {va.x, va.y, va.z, va.w};
            float bv[4] = {vb.x, vb.y, vb.z, vb.w};
            int ptb = rr * 34 + 1 + q * 4;
#pragma unroll
            for (int k = 0; k < 4; k++) {
                __half ha = __float2half_rn(av[k]), hb = __float2half_rn(bv[k]);
                __half la = __float2half_rn(av[k] - __half2float(ha));
                __half lb = __float2half_rn(bv[k] - __half2float(hb));
                *(__half2*)&sAhi[(ptb + k) * 34 + c] = __halves2half2(ha, hb);
                *(__half2*)&sAlo[(ptb + k) * 34 + c] = __halves2half2(la, lb);
            }
        }
        if (tid < 192) {
            int rr = tid / 32, rem = tid & 31;
            int cp = rem >> 1, e = rem & 1;
            int s = e ? 33 : 0;
            int gh = h0 - 1 + rr, gw = w00 - 1 + s;
            int c = cp * 2;
            float v0 = 0.f, v1 = 0.f;
            if ((unsigned)gh < Hd && (unsigned)gw < Wd) {
                const float* p = in + (size_t)(c0 + c) * HW + gh * Wd + gw;
                v0 = p[0]; v1 = p[HW];
            }
            __half h0v = __float2half_rn(v0), h1v = __float2half_rn(v1);
            __half l0v = __float2half_rn(v0 - __half2float(h0v));
            __half l1v = __float2half_rn(v1 - __half2float(h1v));
            int pt = rr * 34 + s;
            *(__half2*)&sAhi[pt * 34 + c] = __halves2half2(h0v, h1v);
            *(__half2*)&sAlo[pt * 34 + c] = __halves2half2(l0v, l1v);
        }

        for (int tap = 0; tap < 9; tap++) {
            __syncthreads();
            {
                int o = tid >> 2, q = (tid & 3) * 8;
                size_t gi = (size_t)(tap * OCpad + ocb + o) * CIN + c0 + q;
                *(uint4*)&sWhi[o * 40 + q] = *(const uint4*)&whi[gi];
                *(uint4*)&sWlo[o * 40 + q] = *(const uint4*)&wlo[gi];
            }
            __syncthreads();
            const int pt0 = (tap / 3 + (wid >> 1)) * 34 + (tap % 3)
                          + (wid & 1) * 16 + (lane >> 2);
#pragma unroll
            for (int ks = 0; ks < 2; ks++) {
                const int kc = ks * 16 + (lane & 3) * 2;
                u32 ah[4], al[4];
                ah[0] = *(const u32*)&sAhi[pt0 * 34 + kc];
                ah[1] = *(const u32*)&sAhi[(pt0 + 8) * 34 + kc];
                ah[2] = *(const u32*)&sAhi[pt0 * 34 + kc + 8];
                ah[3] = *(const u32*)&sAhi[(pt0 + 8) * 34 + kc + 8];
                al[0] = *(const u32*)&sAlo[pt0 * 34 + kc];
                al[1] = *(const u32*)&sAlo[(pt0 + 8) * 34 + kc];
                al[2] = *(const u32*)&sAlo[pt0 * 34 + kc + 8];
                al[3] = *(const u32*)&sAlo[(pt0 + 8) * 34 + kc + 8];
#pragma unroll
                for (int nf = 0; nf < 8; nf++) {
                    if (nf < nfb) {
                        const int n = nf * 8 + (lane >> 2);
                        u32 bh0 = *(const u32*)&sWhi[n * 40 + kc];
                        u32 bh1 = *(const u32*)&sWhi[n * 40 + kc + 8];
                        u32 bl0 = *(const u32*)&sWlo[n * 40 + kc];
                        u32 bl1 = *(const u32*)&sWlo[n * 40 + kc + 8];
                        mma16816(acc[nf], ah, bh0, bh1);
                        mma16816(acc[nf], al, bh0, bh1);
                        mma16816(acc[nf], ah, bl0, bl1);
                    }
                }
            }
        }
    }

    const int orow = h0 + (wid >> 1);
    const int pcol = w00 + (wid & 1) * 16 + (lane >> 2);
    const int pix0 = orow * Wd + pcol;
    const int pix1 = pix0 + 8;
    const int ocl = (lane & 3) * 2;
#pragma unroll
    for (int nf = 0; nf < 8; nf++) {
        if (nf >= nfb) break;
        const int oc = ocb + nf * 8 + ocl;
        const float b0 = sbias[nf * 8 + ocl], b1 = sbias[nf * 8 + ocl + 1];
        float v[4] = {acc[nf][0] + b0, acc[nf][1] + b1,
                      acc[nf][2] + b0, acc[nf][3] + b1};
        const int ocs[4] = {oc, oc + 1, oc, oc + 1};
        const int pxs[4] = {pix0, pix0, pix1, pix1};
#pragma unroll
        for (int t = 0; t < 4; t++) {
            float r = v[t];
            const int o2 = ocs[t], px = pxs[t];
            if (MODE == 0) {
                outf[(size_t)o2 * HW + px] = (r >= 0.f) ? r : 0.1f * r;
            } else if (MODE == 1) {
                outf[(size_t)o2 * HW + px] = r;
            } else {
                if (o2 < 144) {
                    outf[(size_t)o2 * HW + px] =
                        10.0f * tanhf(r) + flow[((size_t)((o2 & 1) ^ 1)) * HW + px];
                } else if (o2 < 216) {
                    outf2[(size_t)(o2 - 144) * HW + px] = 1.0f / (1.0f + expf(-r));
                }
            }
        }
    }
}

// ---------------- mdcn: fp16 NHWC gather + HMMA GEMM ----------------
__global__ __launch_bounds__(256)
void mdcn_kernel(const __half* __restrict__ xt, const float* __restrict__ off,
                 const float* __restrict__ mask, const __half* __restrict__ dwhi,
                 const __half* __restrict__ dwlo, const float* __restrict__ bias,
                 float* __restrict__ out)
{
    __shared__ __align__(16) __half sShi[64 * 90], sSlo[64 * 90];
    __shared__ __align__(16) __half sWhi[64 * 88], sWlo[64 * 88];
    __shared__ float sbias[64];
    const int tid = threadIdx.x;
    const int wid = tid >> 5, lane = tid & 31;
    const int h = blockIdx.y;
    const int col0 = blockIdx.x * 64;
    const int px = tid & 63;
    const int part = tid >> 6;
    const int pixg = col0 + px;
    const int hw = h * Wd + pixg;
    const int k_beg = (part == 0) ? 0 : 1 + part * 2;
    const int k_end = (part == 0) ? 3 : 3 + part * 2;

    if (tid < 64) sbias[tid] = bias[tid];
    for (int i = tid; i < 64 * 8; i += 256) {
        int p = i >> 3, j = i & 7;
        sShi[p * 90 + 72 + j] = __ushort_as_half(0);
        sSlo[p * 90 + 72 + j] = __ushort_as_half(0);
    }

    float acc[8][4];
#pragma unroll
    for (int i = 0; i < 8; i++)
#pragma unroll
        for (int j = 0; j < 4; j++) acc[i][j] = 0.f;

    for (int g = 0; g < 8; g++) {
        __syncthreads();
        {
            const u32* gh32 = (const u32*)(dwhi + g * 5632);
            const u32* gl32 = (const u32*)(dwlo + g * 5632);
            for (int i = tid; i < 2816; i += 256) {
                ((u32*)sWhi)[i] = gh32[i];
                ((u32*)sWlo)[i] = gl32[i];
            }
        }
        for (int k = k_beg; k < k_end; k++) {
            int gk = g * 9 + k;
            float offy = off[(gk * 2 + 0) * HW + hw];
            float offx = off[(gk * 2 + 1) * HW + hw];
            float m    = mask[gk * HW + hw];
            float py = (float)h    + (float)(k / 3 - 1) + offy;
            float pxf = (float)pixg + (float)(k % 3 - 1) + offx;
            float y0f = floorf(py), x0f = floorf(pxf);
            float ly = py - y0f, lx = pxf - x0f;
            int y0 = (int)y0f, x0i = (int)x0f;
            int y1 = y0 + 1,  x1 = x0i + 1;
            bool vy0 = (unsigned)y0 < Hd, vy1 = (unsigned)y1 < Hd;
            bool vx0 = (unsigned)x0i < Wd, vx1 = (unsigned)x1 < Wd;
            int yc0 = min(max(y0, 0), Hd - 1), yc1 = min(max(y1, 0), Hd - 1);
            int xc0 = min(max(x0i, 0), Wd - 1), xc1 = min(max(x1, 0), Wd - 1);
            float w00 = (vy0 && vx0) ? (1.f - ly) * (1.f - lx) * m : 0.f;
            float w01 = (vy0 && vx1) ? (1.f - ly) * lx * m : 0.f;
            float w10 = (vy1 && vx0) ? ly * (1.f - lx) * m : 0.f;
            float w11 = (vy1 && vx1) ? ly * lx * m : 0.f;
            uint4 r00 = *(const uint4*)(xt + ((size_t)(yc0 * Wd + xc0)) * 64 + g * 8);
            uint4 r01 = *(const uint4*)(xt + ((size_t)(yc0 * Wd + xc1)) * 64 + g * 8);
            uint4 r10 = *(const uint4*)(xt + ((size_t)(yc1 * Wd + xc0)) * 64 + g * 8);
            uint4 r11 = *(const uint4*)(xt + ((size_t)(yc1 * Wd + xc1)) * 64 + g * 8);
            const __half2* hA = (const __half2*)&r00;
            const __half2* hB = (const __half2*)&r01;
            const __half2* hC = (const __half2*)&r10;
            const __half2* hD = (const __half2*)&r11;
#pragma unroll
            for (int cc = 0; cc < 4; cc++) {
                float2 fa = __half22float2(hA[cc]);
                float2 fb = __half22float2(hB[cc]);
                float2 fc = __half22float2(hC[cc]);
                float2 fd = __half22float2(hD[cc]);
                float s0 = w00 * fa.x + w01 * fb.x + w10 * fc.x + w11 * fd.x;
                float s1 = w00 * fa.y + w01 * fb.y + w10 * fc.y + w11 * fd.y;
                __half h0 = __float2half_rn(s0), h1 = __float2half_rn(s1);
                sShi[px * 90 + (cc * 2 + 0) * 9 + k] = h0;
                sShi[px * 90 + (cc * 2 + 1) * 9 + k] = h1;
                sSlo[px * 90 + (cc * 2 + 0) * 9 + k] = __float2half_rn(s0 - __half2float(h0));
                sSlo[px * 90 + (cc * 2 + 1) * 9 + k] = __float2half_rn(s1 - __half2float(h1));
            }
        }
        __syncthreads();
        const int mw = wid & 3;
        const int nhalf = (wid >> 2) * 4;
        const int r = mw * 16 + (lane >> 2);
#pragma unroll
        for (int ks = 0; ks < 5; ks++) {
            const int kc = ks * 16 + (lane & 3) * 2;
            u32 ah[4], al[4];
            ah[0] = *(const u32*)&sShi[r * 90 + kc];
            ah[1] = *(const u32*)&sShi[(r + 8) * 90 + kc];
            ah[2] = *(const u32*)&sShi[r * 90 + kc + 8];
            ah[3] = *(const u32*)&sShi[(r + 8) * 90 + kc + 8];
            al[0] = *(const u32*)&sSlo[r * 90 + kc];
            al[1] = *(const u32*)&sSlo[(r + 8) * 90 + kc];
            al[2] = *(const u32*)&sSlo[r * 90 + kc + 8];
            al[3] = *(const u32*)&sSlo[(r + 8) * 90 + kc + 8];
#pragma unroll
            for (int nf = 0; nf < 4; nf++) {
                const int n = (nhalf + nf) * 8 + (lane >> 2);
                u32 bh0 = *(const u32*)&sWhi[n * 88 + kc];
                u32 bh1 = *(const u32*)&sWhi[n * 88 + kc + 8];
                u32 bl0 = *(const u32*)&sWlo[n * 88 + kc];
                u32 bl1 = *(const u32*)&sWlo[n * 88 + kc + 8];
                mma16816(acc[nf], ah, bh0, bh1);
                mma16816(acc[nf], al, bh0, bh1);
                mma16816(acc[nf], ah, bl0, bl1);
            }
        }
    }
    const int mw = wid & 3, nhalf = (wid >> 2) * 4;
    const int p1 = col0 + mw * 16 + (lane >> 2);
    const int p2 = p1 + 8;
    const int oc0 = (lane & 3) * 2;
#pragma unroll
    for (int nf = 0; nf < 4; nf++) {
        const int oc = (nhalf + nf) * 8 + oc0;
        out[(size_t)oc * HW + h * Wd + p1]       = acc[nf][0] + sbias[oc];
        out[(size_t)(oc + 1) * HW + h * Wd + p1] = acc[nf][1] + sbias[oc + 1];
        out[(size_t)oc * HW + h * Wd + p2]       = acc[nf][2] + sbias[oc];
        out[(size_t)(oc + 1) * HW + h * Wd + p2] = acc[nf][3] + sbias[oc + 1];
    }
}

// ---------------- host orchestration ----------------
extern "C" void kernel_launch(void* const* d_in, const int* in_sizes, int n_in,
                              void* d_out, int out_size)
{
    const float* feat_prev       = (const float*)d_in[0];
    const float* feat_next       = (const float*)d_in[1];
    const float* extra_feat_prev = (const float*)d_in[2];
    const float* extra_feat_next = (const float*)d_in[3];
    const float* flow_prev       = (const float*)d_in[4];
    const float* flow_next       = (const float*)d_in[5];
    const float* o1b[4] = {(const float*)d_in[7],  (const float*)d_in[9],
                           (const float*)d_in[11], (const float*)d_in[13]};
    const float* o2b[4] = {(const float*)d_in[15], (const float*)d_in[17],
                           (const float*)d_in[19], (const float*)d_in[21]};
    const float* dcn1_w = (const float*)d_in[22];
    const float* dcn1_b = (const float*)d_in[23];
    const float* dcn2_w = (const float*)d_in[24];
    const float* dcn2_b = (const float*)d_in[25];
    const float* fus_b  = (const float*)d_in[27];
    float* out = (float*)d_out;

    float *ba, *bb, *offp, *maskp, *catp;
    __half *xt, *whi, *wlo, *dwhi, *dwlo;
    cudaGetSymbolAddress((void**)&ba, g_buf_a);
    cudaGetSymbolAddress((void**)&bb, g_buf_b);
    cudaGetSymbolAddress((void**)&offp,  g_off);
    cudaGetSymbolAddress((void**)&maskp, g_mask);
    cudaGetSymbolAddress((void**)&catp,  g_cat);
    cudaGetSymbolAddress((void**)&xt,    g_xt);
    cudaGetSymbolAddress((void**)&whi, g_whi);
    cudaGetSymbolAddress((void**)&wlo, g_wlo);
    cudaGetSymbolAddress((void**)&dwhi, g_dwhi);
    cudaGetSymbolAddress((void**)&dwlo, g_dwlo);

    WSrc ws;
    ws.p[0] = (const float*)d_in[6];  ws.p[1] = (const float*)d_in[8];
    ws.p[2] = (const float*)d_in[10]; ws.p[3] = (const float*)d_in[12];
    ws.p[4] = (const float*)d_in[14]; ws.p[5] = (const float*)d_in[16];
    ws.p[6] = (const float*)d_in[18]; ws.p[7] = (const float*)d_in[20];
    ws.p[8] = (const float*)d_in[26];
    wprep_all<<<(663552 + 255) / 256, 256>>>(ws, whi, wlo);
    dcnprep_all<<<dim3(176, 2), 256>>>(dcn1_w, dcn2_w, dwhi, dwlo);
    tohwc_kernel<<<512, 128>>>(feat_prev, xt);          // branch-prev feat (used before overwrite)

    dim3 g1(512, 1), g4(512, 4), mg(4, 256);

    gconv_kernel<2,0><<<g1, 256>>>(extra_feat_prev, whi + 0, wlo + 0, o1b[0], 64, 64, ba, nullptr, nullptr);
    gconv_kernel<1,0><<<g1, 256>>>(ba, whi + 73728, wlo + 73728, o1b[1], 64, 64, bb, nullptr, nullptr);
    gconv_kernel<1,0><<<g1, 256>>>(bb, whi + 110592, wlo + 110592, o1b[2], 64, 64, ba, nullptr, nullptr);
    gconv_kernel<1,2><<<g4, 256>>>(ba, whi + 147456, wlo + 147456, o1b[3], 216, 256, offp, maskp, flow_prev);
    mdcn_kernel<<<mg, 256>>>(xt, offp, maskp, dwhi, dwlo, dcn1_b, catp);

    gconv_kernel<2,0><<<g1, 256>>>(extra_feat_next, whi + 294912, wlo + 294912, o2b[0], 64, 64, ba, nullptr, nullptr);
    gconv_kernel<1,0><<<g1, 256>>>(ba, whi + 368640, wlo + 368640, o2b[1], 64, 64, bb, nullptr, nullptr);
    gconv_kernel<1,0><<<g1, 256>>>(bb, whi + 405504, wlo + 405504, o2b[2], 64, 64, ba, nullptr, nullptr);
    gconv_kernel<1,2><<<g4, 256>>>(ba, whi + 442368, wlo + 442368, o2b[3], 216, 256, offp, maskp, flow_next);
    tohwc_kernel<<<512, 128>>>(feat_next, xt);
    mdcn_kernel<<<mg, 256>>>(xt, offp, maskp, dwhi + 45056, dwlo + 45056, dcn2_b, catp + (size_t)64 * HW);

    gconv_kernel<2,1><<<g1, 256>>>(catp, whi + 589824, wlo + 589824, fus_b, 64, 64, out, nullptr, nullptr);
}

// round 12
// speedup vs baseline: 4.9029x; 1.0759x over previous
#include <cuda_runtime.h>
#include <cuda_fp16.h>
#include <math.h>

#define Wd 256
#define Hd 256
#define HW 65536
typedef unsigned int u32;

// ---------------- scratch (no allocation allowed) ----------------
__device__ float g_buf_a[64 * HW];
__device__ float g_buf_b[64 * HW];
__device__ float g_off [144 * HW];
__device__ float g_mask[ 72 * HW];
__device__ float g_cat [128 * HW];
__device__ __align__(16) __half g_xt[64 * HW];          // NHWC feat, fp16
__device__ __align__(16) __half g_whi[663552];
__device__ __align__(16) __half g_wlo[663552];
__device__ __align__(16) __half g_dwhi[2 * 45056];
__device__ __align__(16) __half g_dwlo[2 * 45056];

// ---------------- merged conv-weight pre-convert ----------------
struct WSrc { const float* p[9]; };
__global__ void wprep_all(WSrc ws, __half* __restrict__ dhi, __half* __restrict__ dlo)
{
    const int off[9]  = {0,73728,110592,147456,294912,368640,405504,442368,589824};
    const int CINs[9] = {128,64,64,64,128,64,64,64,128};
    const int OCs[9]  = {64,64,64,216,64,64,64,216,64};
    const int OCp[9]  = {64,64,64,256,64,64,64,256,64};
    int idx = blockIdx.x * 256 + threadIdx.x;
    if (idx >= 663552) return;
    int seg = 0;
#pragma unroll
    for (int s = 1; s < 9; s++) if (idx >= off[s]) seg = s;
    int r = idx - off[seg];
    int per_t = OCp[seg] * CINs[seg];
    int t = r / per_t; r -= t * per_t;
    int o = r / CINs[seg], c = r - o * CINs[seg];
    float w = (o < OCs[seg]) ? ws.p[seg][(o * CINs[seg] + c) * 9 + t] : 0.f;
    __half h = __float2half_rn(w);
    dhi[idx] = h;
    dlo[idx] = __float2half_rn(w - __half2float(h));
}

// ---------------- dcn weight pre-convert: both branches ----------------
__global__ void dcnprep_all(const float* __restrict__ s1, const float* __restrict__ s2,
                            __half* __restrict__ dhi, __half* __restrict__ dlo)
{
    int idx = blockIdx.x * 256 + threadIdx.x;
    if (idx >= 45056) return;
    const float* src = blockIdx.y ? s2 : s1;
    int base = blockIdx.y * 45056;
    int g = idx / 5632, r = idx - g * 5632, o = r / 88, ck = r - o * 88;
    float w = 0.f;
    if (ck < 72) { int c = ck / 9, k = ck - c * 9; w = src[((size_t)o * 64 + g * 8 + c) * 9 + k]; }
    __half h = __float2half_rn(w);
    dhi[base + idx] = h;
    dlo[base + idx] = __float2half_rn(w - __half2float(h));
}

// ---------------- NCHW fp32 -> NHWC fp16 ----------------
__global__ __launch_bounds__(128)
void tohwc_kernel(const float* __restrict__ src, __half* __restrict__ dst)
{
    __shared__ float s[64 * 130];
    const int t = threadIdx.x;
    const int pix0 = blockIdx.x * 128;
    for (int c = 0; c < 64; c++) s[c * 130 + t] = src[(size_t)c * HW + pix0 + t];
    __syncthreads();
    for (int i = 0; i < 64; i++) {
        int L = t + i * 128;
        dst[(size_t)pix0 * 64 + L] = __float2half_rn(s[(L & 63) * 130 + (L >> 6)]);
    }
}

__device__ __forceinline__ void mma16816(float* d, const u32* a, u32 b0, u32 b1) {
    asm volatile(
        "mma.sync.aligned.m16n8k16.row.col.f32.f16.f16.f32 "
        "{%0,%1,%2,%3}, {%4,%5,%6,%7}, {%8,%9}, {%0,%1,%2,%3};"
        : "+f"(d[0]), "+f"(d[1]), "+f"(d[2]), "+f"(d[3])
        : "r"(a[0]), "r"(a[1]), "r"(a[2]), "r"(a[3]), "r"(b0), "r"(b1));
}

// ---------------- HMMA implicit-GEMM 3x3 conv ----------------
// 256 thr (8 warps). Tile: 8 rows x 32 px (M=256) x 64 oc. Warp w owns row w
// (two m16 slabs). Strip: 10 rows x 34 px x 32 ch hi/lo in dynamic smem.
// smem layout (bytes): sAhi@0 (23120), sAlo@23120, sWhi@46240 (5120),
//                      sWlo@51360, sbias@56480. Total 56736.
#define GSM 56832
template<int NCB, int MODE>
__global__ __launch_bounds__(256)
void gconv_kernel(const float* __restrict__ in, const __half* __restrict__ whi,
                  const __half* __restrict__ wlo, const float* __restrict__ bias,
                  int oc_total, int OCpad,
                  float* __restrict__ outf, float* __restrict__ outf2,
                  const float* __restrict__ flow)
{
    extern __shared__ char smem_[];
    __half* sAhi = (__half*)smem_;
    __half* sAlo = (__half*)(smem_ + 23120);
    __half* sWhi = (__half*)(smem_ + 46240);
    __half* sWlo = (__half*)(smem_ + 51360);
    float* sbias = (float*)(smem_ + 56480);

    const int tid = threadIdx.x;
    const int wid = tid >> 5, lane = tid & 31;
    const int h0 = (blockIdx.x >> 3) * 8;
    const int w00 = (blockIdx.x & 7) * 32;
    const int ocb = blockIdx.y * 64;
    const int CIN = NCB * 64;
    int nfb = (oc_total - ocb + 7) >> 3; if (nfb > 8) nfb = 8;

    if (tid < 64) sbias[tid] = (ocb + tid < oc_total) ? bias[ocb + tid] : 0.f;

    float acc0[8][4], acc1[8][4];
#pragma unroll
    for (int i = 0; i < 8; i++)
#pragma unroll
        for (int j = 0; j < 4; j++) { acc0[i][j] = 0.f; acc1[i][j] = 0.f; }

    for (int cb = 0; cb < NCB; cb++)
    for (int hf = 0; hf < 2; hf++) {
        const int c0 = cb * 64 + hf * 32;
        __syncthreads();
        // ---- stage strip interior: 10 rows x 32 cols x 32 ch (1280 jobs) ----
#pragma unroll
        for (int i = 0; i < 5; i++) {
            int j = tid + i * 256;
            int rr = j >> 7, rem = j & 127;
            int cp = rem >> 3, q = rem & 7;
            int gh = h0 - 1 + rr;
            int c = cp * 2;
            float4 va = make_float4(0.f, 0.f, 0.f, 0.f), vb = va;
            if ((unsigned)gh < Hd) {
                const float* p = in + (size_t)(c0 + c) * HW + gh * Wd + (w00 + q * 4);
                va = *(const float4*)p;
                vb = *(const float4*)(p + HW);
            }
            float av[4] = {va.x, va.y, va.z, va.w};
            float bv[4] = {vb.x, vb.y, vb.z, vb.w};
            int ptb = rr * 34 + 1 + q * 4;
#pragma unroll
            for (int k = 0; k < 4; k++) {
                __half ha = __float2half_rn(av[k]), hb = __float2half_rn(bv[k]);
                __half la = __float2half_rn(av[k] - __half2float(ha));
                __half lb = __float2half_rn(bv[k] - __half2float(hb));
                *(__half2*)&sAhi[(ptb + k) * 34 + c] = __halves2half2(ha, hb);
                *(__half2*)&sAlo[(ptb + k) * 34 + c] = __halves2half2(la, lb);
            }
        }
        // ---- edges s=0, s=33: 10 rows x 16 cpairs x 2 (320 jobs) ----
#pragma unroll
        for (int i = 0; i < 2; i++) {
            int j = tid + i * 256;
            if (j < 320) {
                int rr = j >> 5, rem = j & 31;
                int cp = rem >> 1, e = rem & 1;
                int s = e ? 33 : 0;
                int gh = h0 - 1 + rr, gw = w00 - 1 + s;
                int c = cp * 2;
                float v0 = 0.f, v1 = 0.f;
                if ((unsigned)gh < Hd && (unsigned)gw < Wd) {
                    const float* p = in + (size_t)(c0 + c) * HW + gh * Wd + gw;
                    v0 = p[0]; v1 = p[HW];
                }
                __half h0v = __float2half_rn(v0), h1v = __float2half_rn(v1);
                __half l0v = __float2half_rn(v0 - __half2float(h0v));
                __half l1v = __float2half_rn(v1 - __half2float(h1v));
                int pt = rr * 34 + s;
                *(__half2*)&sAhi[pt * 34 + c] = __halves2half2(h0v, h1v);
                *(__half2*)&sAlo[pt * 34 + c] = __halves2half2(l0v, l1v);
            }
        }

        for (int tap = 0; tap < 9; tap++) {
            __syncthreads();
            {
                int o = tid >> 2, q = (tid & 3) * 8;
                size_t gi = (size_t)(tap * OCpad + ocb + o) * CIN + c0 + q;
                *(uint4*)&sWhi[o * 40 + q] = *(const uint4*)&whi[gi];
                *(uint4*)&sWlo[o * 40 + q] = *(const uint4*)&wlo[gi];
            }
            __syncthreads();
            const int base = (tap / 3 + wid) * 34 + (tap % 3) + (lane >> 2);
#pragma unroll
            for (int ks = 0; ks < 2; ks++) {
                const int kc = ks * 16 + (lane & 3) * 2;
                u32 ah0[4], al0[4], ah1[4], al1[4];
                ah0[0] = *(const u32*)&sAhi[base * 34 + kc];
                ah0[1] = *(const u32*)&sAhi[(base + 8) * 34 + kc];
                ah0[2] = *(const u32*)&sAhi[base * 34 + kc + 8];
                ah0[3] = *(const u32*)&sAhi[(base + 8) * 34 + kc + 8];
                al0[0] = *(const u32*)&sAlo[base * 34 + kc];
                al0[1] = *(const u32*)&sAlo[(base + 8) * 34 + kc];
                al0[2] = *(const u32*)&sAlo[base * 34 + kc + 8];
                al0[3] = *(const u32*)&sAlo[(base + 8) * 34 + kc + 8];
                ah1[0] = *(const u32*)&sAhi[(base + 16) * 34 + kc];
                ah1[1] = *(const u32*)&sAhi[(base + 24) * 34 + kc];
                ah1[2] = *(const u32*)&sAhi[(base + 16) * 34 + kc + 8];
                ah1[3] = *(const u32*)&sAhi[(base + 24) * 34 + kc + 8];
                al1[0] = *(const u32*)&sAlo[(base + 16) * 34 + kc];
                al1[1] = *(const u32*)&sAlo[(base + 24) * 34 + kc];
                al1[2] = *(const u32*)&sAlo[(base + 16) * 34 + kc + 8];
                al1[3] = *(const u32*)&sAlo[(base + 24) * 34 + kc + 8];
#pragma unroll
                for (int nf = 0; nf < 8; nf++) {
                    if (nf < nfb) {
                        const int n = nf * 8 + (lane >> 2);
                        u32 bh0 = *(const u32*)&sWhi[n * 40 + kc];
                        u32 bh1 = *(const u32*)&sWhi[n * 40 + kc + 8];
                        u32 bl0 = *(const u32*)&sWlo[n * 40 + kc];
                        u32 bl1 = *(const u32*)&sWlo[n * 40 + kc + 8];
                        mma16816(acc0[nf], ah0, bh0, bh1);
                        mma16816(acc0[nf], al0, bh0, bh1);
                        mma16816(acc0[nf], ah0, bl0, bl1);
                        mma16816(acc1[nf], ah1, bh0, bh1);
                        mma16816(acc1[nf], al1, bh0, bh1);
                        mma16816(acc1[nf], ah1, bl0, bl1);
                    }
                }
            }
        }
    }

    // ---- epilogue: warp w = row h0+w; slab0 cols 0-15, slab1 cols 16-31 ----
    const int row = h0 + wid;
    const int pbase = row * Wd + w00 + (lane >> 2);
    const int ocl = (lane & 3) * 2;
#pragma unroll
    for (int nf = 0; nf < 8; nf++) {
        if (nf >= nfb) break;
        const int oc = ocb + nf * 8 + ocl;
        const float b0 = sbias[nf * 8 + ocl], b1 = sbias[nf * 8 + ocl + 1];
#pragma unroll
        for (int sl = 0; sl < 2; sl++) {
            const float* a = sl ? acc1[nf] : acc0[nf];
            const int pb = pbase + sl * 16;
            float v[4] = {a[0] + b0, a[1] + b1, a[2] + b0, a[3] + b1};
            const int ocs[4] = {oc, oc + 1, oc, oc + 1};
            const int pxs[4] = {pb, pb, pb + 8, pb + 8};
#pragma unroll
            for (int t = 0; t < 4; t++) {
                float r = v[t];
                const int o2 = ocs[t], px = pxs[t];
                if (MODE == 0) {
                    outf[(size_t)o2 * HW + px] = (r >= 0.f) ? r : 0.1f * r;
                } else if (MODE == 1) {
                    outf[(size_t)o2 * HW + px] = r;
                } else {
                    if (o2 < 144) {
                        outf[(size_t)o2 * HW + px] =
                            10.0f * tanhf(r) + flow[((size_t)((o2 & 1) ^ 1)) * HW + px];
                    } else if (o2 < 216) {
                        outf2[(size_t)(o2 - 144) * HW + px] = 1.0f / (1.0f + expf(-r));
                    }
                }
            }
        }
    }
}

// ---------------- mdcn: fp16 NHWC gather + HMMA GEMM (unchanged) ----------------
__global__ __launch_bounds__(256)
void mdcn_kernel(const __half* __restrict__ xt, const float* __restrict__ off,
                 const float* __restrict__ mask, const __half* __restrict__ dwhi,
                 const __half* __restrict__ dwlo, const float* __restrict__ bias,
                 float* __restrict__ out)
{
    __shared__ __align__(16) __half sShi[64 * 90], sSlo[64 * 90];
    __shared__ __align__(16) __half sWhi[64 * 88], sWlo[64 * 88];
    __shared__ float sbias[64];
    const int tid = threadIdx.x;
    const int wid = tid >> 5, lane = tid & 31;
    const int h = blockIdx.y;
    const int col0 = blockIdx.x * 64;
    const int px = tid & 63;
    const int part = tid >> 6;
    const int pixg = col0 + px;
    const int hw = h * Wd + pixg;
    const int k_beg = (part == 0) ? 0 : 1 + part * 2;
    const int k_end = (part == 0) ? 3 : 3 + part * 2;

    if (tid < 64) sbias[tid] = bias[tid];
    for (int i = tid; i < 64 * 8; i += 256) {
        int p = i >> 3, j = i & 7;
        sShi[p * 90 + 72 + j] = __ushort_as_half(0);
        sSlo[p * 90 + 72 + j] = __ushort_as_half(0);
    }

    float acc[8][4];
#pragma unroll
    for (int i = 0; i < 8; i++)
#pragma unroll
        for (int j = 0; j < 4; j++) acc[i][j] = 0.f;

    for (int g = 0; g < 8; g++) {
        __syncthreads();
        {
            const u32* gh32 = (const u32*)(dwhi + g * 5632);
            const u32* gl32 = (const u32*)(dwlo + g * 5632);
            for (int i = tid; i < 2816; i += 256) {
                ((u32*)sWhi)[i] = gh32[i];
                ((u32*)sWlo)[i] = gl32[i];
            }
        }
        for (int k = k_beg; k < k_end; k++) {
            int gk = g * 9 + k;
            float offy = off[(gk * 2 + 0) * HW + hw];
            float offx = off[(gk * 2 + 1) * HW + hw];
            float m    = mask[gk * HW + hw];
            float py = (float)h    + (float)(k / 3 - 1) + offy;
            float pxf = (float)pixg + (float)(k % 3 - 1) + offx;
            float y0f = floorf(py), x0f = floorf(pxf);
            float ly = py - y0f, lx = pxf - x0f;
            int y0 = (int)y0f, x0i = (int)x0f;
            int y1 = y0 + 1,  x1 = x0i + 1;
            bool vy0 = (unsigned)y0 < Hd, vy1 = (unsigned)y1 < Hd;
            bool vx0 = (unsigned)x0i < Wd, vx1 = (unsigned)x1 < Wd;
            int yc0 = min(max(y0, 0), Hd - 1), yc1 = min(max(y1, 0), Hd - 1);
            int xc0 = min(max(x0i, 0), Wd - 1), xc1 = min(max(x1, 0), Wd - 1);
            float w00 = (vy0 && vx0) ? (1.f - ly) * (1.f - lx) * m : 0.f;
            float w01 = (vy0 && vx1) ? (1.f - ly) * lx * m : 0.f;
            float w10 = (vy1 && vx0) ? ly * (1.f - lx) * m : 0.f;
            float w11 = (vy1 && vx1) ? ly * lx * m : 0.f;
            uint4 r00 = *(const uint4*)(xt + ((size_t)(yc0 * Wd + xc0)) * 64 + g * 8);
            uint4 r01 = *(const uint4*)(xt + ((size_t)(yc0 * Wd + xc1)) * 64 + g * 8);
            uint4 r10 = *(const uint4*)(xt + ((size_t)(yc1 * Wd + xc0)) * 64 + g * 8);
            uint4 r11 = *(const uint4*)(xt + ((size_t)(yc1 * Wd + xc1)) * 64 + g * 8);
            const __half2* hA = (const __half2*)&r00;
            const __half2* hB = (const __half2*)&r01;
            const __half2* hC = (const __half2*)&r10;
            const __half2* hD = (const __half2*)&r11;
#pragma unroll
            for (int cc = 0; cc < 4; cc++) {
                float2 fa = __half22float2(hA[cc]);
                float2 fb = __half22float2(hB[cc]);
                float2 fc = __half22float2(hC[cc]);
                float2 fd = __half22float2(hD[cc]);
                float s0 = w00 * fa.x + w01 * fb.x + w10 * fc.x + w11 * fd.x;
                float s1 = w00 * fa.y + w01 * fb.y + w10 * fc.y + w11 * fd.y;
                __half h0 = __float2half_rn(s0), h1 = __float2half_rn(s1);
                sShi[px * 90 + (cc * 2 + 0) * 9 + k] = h0;
                sShi[px * 90 + (cc * 2 + 1) * 9 + k] = h1;
                sSlo[px * 90 + (cc * 2 + 0) * 9 + k] = __float2half_rn(s0 - __half2float(h0));
                sSlo[px * 90 + (cc * 2 + 1) * 9 + k] = __float2half_rn(s1 - __half2float(h1));
            }
        }
        __syncthreads();
        const int mw = wid & 3;
        const int nhalf = (wid >> 2) * 4;
        const int r = mw * 16 + (lane >> 2);
#pragma unroll
        for (int ks = 0; ks < 5; ks++) {
            const int kc = ks * 16 + (lane & 3) * 2;
            u32 ah[4], al[4];
            ah[0] = *(const u32*)&sShi[r * 90 + kc];
            ah[1] = *(const u32*)&sShi[(r + 8) * 90 + kc];
            ah[2] = *(const u32*)&sShi[r * 90 + kc + 8];
            ah[3] = *(const u32*)&sShi[(r + 8) * 90 + kc + 8];
            al[0] = *(const u32*)&sSlo[r * 90 + kc];
            al[1] = *(const u32*)&sSlo[(r + 8) * 90 + kc];
            al[2] = *(const u32*)&sSlo[r * 90 + kc + 8];
            al[3] = *(const u32*)&sSlo[(r + 8) * 90 + kc + 8];
#pragma unroll
            for (int nf = 0; nf < 4; nf++) {
                const int n = (nhalf + nf) * 8 + (lane >> 2);
                u32 bh0 = *(const u32*)&sWhi[n * 88 + kc];
                u32 bh1 = *(const u32*)&sWhi[n * 88 + kc + 8];
                u32 bl0 = *(const u32*)&sWlo[n * 88 + kc];
                u32 bl1 = *(const u32*)&sWlo[n * 88 + kc + 8];
                mma16816(acc[nf], ah, bh0, bh1);
                mma16816(acc[nf], al, bh0, bh1);
                mma16816(acc[nf], ah, bl0, bl1);
            }
        }
    }
    const int mw = wid & 3, nhalf = (wid >> 2) * 4;
    const int p1 = col0 + mw * 16 + (lane >> 2);
    const int p2 = p1 + 8;
    const int oc0 = (lane & 3) * 2;
#pragma unroll
    for (int nf = 0; nf < 4; nf++) {
        const int oc = (nhalf + nf) * 8 + oc0;
        out[(size_t)oc * HW + h * Wd + p1]       = acc[nf][0] + sbias[oc];
        out[(size_t)(oc + 1) * HW + h * Wd + p1] = acc[nf][1] + sbias[oc + 1];
        out[(size_t)oc * HW + h * Wd + p2]       = acc[nf][2] + sbias[oc];
        out[(size_t)(oc + 1) * HW + h * Wd + p2] = acc[nf][3] + sbias[oc + 1];
    }
}

// ---------------- host orchestration ----------------
extern "C" void kernel_launch(void* const* d_in, const int* in_sizes, int n_in,
                              void* d_out, int out_size)
{
    const float* feat_prev       = (const float*)d_in[0];
    const float* feat_next       = (const float*)d_in[1];
    const float* extra_feat_prev = (const float*)d_in[2];
    const float* extra_feat_next = (const float*)d_in[3];
    const float* flow_prev       = (const float*)d_in[4];
    const float* flow_next       = (const float*)d_in[5];
    const float* o1b[4] = {(const float*)d_in[7],  (const float*)d_in[9],
                           (const float*)d_in[11], (const float*)d_in[13]};
    const float* o2b[4] = {(const float*)d_in[15], (const float*)d_in[17],
                           (const float*)d_in[19], (const float*)d_in[21]};
    const float* dcn1_w = (const float*)d_in[22];
    const float* dcn1_b = (const float*)d_in[23];
    const float* dcn2_w = (const float*)d_in[24];
    const float* dcn2_b = (const float*)d_in[25];
    const float* fus_b  = (const float*)d_in[27];
    float* out = (float*)d_out;

    float *ba, *bb, *offp, *maskp, *catp;
    __half *xt, *whi, *wlo, *dwhi, *dwlo;
    cudaGetSymbolAddress((void**)&ba, g_buf_a);
    cudaGetSymbolAddress((void**)&bb, g_buf_b);
    cudaGetSymbolAddress((void**)&offp,  g_off);
    cudaGetSymbolAddress((void**)&maskp, g_mask);
    cudaGetSymbolAddress((void**)&catp,  g_cat);
    cudaGetSymbolAddress((void**)&xt,    g_xt);
    cudaGetSymbolAddress((void**)&whi, g_whi);
    cudaGetSymbolAddress((void**)&wlo, g_wlo);
    cudaGetSymbolAddress((void**)&dwhi, g_dwhi);
    cudaGetSymbolAddress((void**)&dwlo, g_dwlo);

    // dynamic-smem opt-in (idempotent; executes immediately, not a graph node)
    cudaFuncSetAttribute(gconv_kernel<2,0>, cudaFuncAttributeMaxDynamicSharedMemorySize, GSM);
    cudaFuncSetAttribute(gconv_kernel<1,0>, cudaFuncAttributeMaxDynamicSharedMemorySize, GSM);
    cudaFuncSetAttribute(gconv_kernel<1,2>, cudaFuncAttributeMaxDynamicSharedMemorySize, GSM);
    cudaFuncSetAttribute(gconv_kernel<2,1>, cudaFuncAttributeMaxDynamicSharedMemorySize, GSM);

    WSrc ws;
    ws.p[0] = (const float*)d_in[6];  ws.p[1] = (const float*)d_in[8];
    ws.p[2] = (const float*)d_in[10]; ws.p[3] = (const float*)d_in[12];
    ws.p[4] = (const float*)d_in[14]; ws.p[5] = (const float*)d_in[16];
    ws.p[6] = (const float*)d_in[18]; ws.p[7] = (const float*)d_in[20];
    ws.p[8] = (const float*)d_in[26];
    wprep_all<<<(663552 + 255) / 256, 256>>>(ws, whi, wlo);
    dcnprep_all<<<dim3(176, 2), 256>>>(dcn1_w, dcn2_w, dwhi, dwlo);
    tohwc_kernel<<<512, 128>>>(feat_prev, xt);

    dim3 g1(256, 1), g4(256, 4), mg(4, 256);

    gconv_kernel<2,0><<<g1, 256, GSM>>>(extra_feat_prev, whi + 0, wlo + 0, o1b[0], 64, 64, ba, nullptr, nullptr);
    gconv_kernel<1,0><<<g1, 256, GSM>>>(ba, whi + 73728, wlo + 73728, o1b[1], 64, 64, bb, nullptr, nullptr);
    gconv_kernel<1,0><<<g1, 256, GSM>>>(bb, whi + 110592, wlo + 110592, o1b[2], 64, 64, ba, nullptr, nullptr);
    gconv_kernel<1,2><<<g4, 256, GSM>>>(ba, whi + 147456, wlo + 147456, o1b[3], 216, 256, offp, maskp, flow_prev);
    mdcn_kernel<<<mg, 256>>>(xt, offp, maskp, dwhi, dwlo, dcn1_b, catp);

    gconv_kernel<2,0><<<g1, 256, GSM>>>(extra_feat_next, whi + 294912, wlo + 294912, o2b[0], 64, 64, ba, nullptr, nullptr);
    gconv_kernel<1,0><<<g1, 256, GSM>>>(ba, whi + 368640, wlo + 368640, o2b[1], 64, 64, bb, nullptr, nullptr);
    gconv_kernel<1,0><<<g1, 256, GSM>>>(bb, whi + 405504, wlo + 405504, o2b[2], 64, 64, ba, nullptr, nullptr);
    gconv_kernel<1,2><<<g4, 256, GSM>>>(ba, whi + 442368, wlo + 442368, o2b[3], 216, 256, offp, maskp, flow_next);
    tohwc_kernel<<<512, 128>>>(feat_next, xt);
    mdcn_kernel<<<mg, 256>>>(xt, offp, maskp, dwhi + 45056, dwlo + 45056, dcn2_b, catp + (size_t)64 * HW);

    gconv_kernel<2,1><<<g1, 256, GSM>>>(catp, whi + 589824, wlo + 589824, fus_b, 64, 64, out, nullptr, nullptr);
}

// round 13
// speedup vs baseline: 5.2718x; 1.0753x over previous
#include <cuda_runtime.h>
#include <cuda_fp16.h>
#include <math.h>

#define Wd 256
#define Hd 256
#define HW 65536
typedef unsigned int u32;

// ---------------- scratch (no allocation allowed) ----------------
__device__ float g_buf_a[64 * HW];
__device__ float g_buf_b[64 * HW];
__device__ float g_off [144 * HW];
__device__ float g_mask[ 72 * HW];
__device__ float g_cat [128 * HW];
__device__ __align__(16) __half g_xt[64 * HW];          // NHWC feat, fp16
__device__ __align__(16) __half g_whi[663552];
__device__ __align__(16) __half g_wlo[663552];
__device__ __align__(16) __half g_dwhi[2 * 45056];
__device__ __align__(16) __half g_dwlo[2 * 45056];

// ---------------- merged conv-weight pre-convert ----------------
struct WSrc { const float* p[9]; };
__global__ void wprep_all(WSrc ws, __half* __restrict__ dhi, __half* __restrict__ dlo)
{
    const int off[9]  = {0,73728,110592,147456,294912,368640,405504,442368,589824};
    const int CINs[9] = {128,64,64,64,128,64,64,64,128};
    const int OCs[9]  = {64,64,64,216,64,64,64,216,64};
    const int OCp[9]  = {64,64,64,256,64,64,64,256,64};
    int idx = blockIdx.x * 256 + threadIdx.x;
    if (idx >= 663552) return;
    int seg = 0;
#pragma unroll
    for (int s = 1; s < 9; s++) if (idx >= off[s]) seg = s;
    int r = idx - off[seg];
    int per_t = OCp[seg] * CINs[seg];
    int t = r / per_t; r -= t * per_t;
    int o = r / CINs[seg], c = r - o * CINs[seg];
    float w = (o < OCs[seg]) ? ws.p[seg][(o * CINs[seg] + c) * 9 + t] : 0.f;
    __half h = __float2half_rn(w);
    dhi[idx] = h;
    dlo[idx] = __float2half_rn(w - __half2float(h));
}

// ---------------- dcn weight pre-convert: both branches ----------------
__global__ void dcnprep_all(const float* __restrict__ s1, const float* __restrict__ s2,
                            __half* __restrict__ dhi, __half* __restrict__ dlo)
{
    int idx = blockIdx.x * 256 + threadIdx.x;
    if (idx >= 45056) return;
    const float* src = blockIdx.y ? s2 : s1;
    int base = blockIdx.y * 45056;
    int g = idx / 5632, r = idx - g * 5632, o = r / 88, ck = r - o * 88;
    float w = 0.f;
    if (ck < 72) { int c = ck / 9, k = ck - c * 9; w = src[((size_t)o * 64 + g * 8 + c) * 9 + k]; }
    __half h = __float2half_rn(w);
    dhi[base + idx] = h;
    dlo[base + idx] = __float2half_rn(w - __half2float(h));
}

// ---------------- NCHW fp32 -> NHWC fp16 ----------------
__global__ __launch_bounds__(128)
void tohwc_kernel(const float* __restrict__ src, __half* __restrict__ dst)
{
    __shared__ float s[64 * 130];
    const int t = threadIdx.x;
    const int pix0 = blockIdx.x * 128;
    for (int c = 0; c < 64; c++) s[c * 130 + t] = src[(size_t)c * HW + pix0 + t];
    __syncthreads();
    for (int i = 0; i < 64; i++) {
        int L = t + i * 128;
        dst[(size_t)pix0 * 64 + L] = __float2half_rn(s[(L & 63) * 130 + (L >> 6)]);
    }
}

__device__ __forceinline__ void mma16816(float* d, const u32* a, u32 b0, u32 b1) {
    asm volatile(
        "mma.sync.aligned.m16n8k16.row.col.f32.f16.f16.f32 "
        "{%0,%1,%2,%3}, {%4,%5,%6,%7}, {%8,%9}, {%0,%1,%2,%3};"
        : "+f"(d[0]), "+f"(d[1]), "+f"(d[2]), "+f"(d[3])
        : "r"(a[0]), "r"(a[1]), "r"(a[2]), "r"(a[3]), "r"(b0), "r"(b1));
}
__device__ __forceinline__ void ldsm4(u32* r, u32 addr) {
    asm volatile("ldmatrix.sync.aligned.m8n8.x4.shared.b16 {%0,%1,%2,%3}, [%4];"
                 : "=r"(r[0]), "=r"(r[1]), "=r"(r[2]), "=r"(r[3]) : "r"(addr));
}
__device__ __forceinline__ u32 smem_u32(const void* p) {
    return (u32)__cvta_generic_to_shared(p);
}

// ---------------- HMMA implicit-GEMM 3x3 conv (ldmatrix + W dbuf) ----------------
// 256 thr (8 warps). Tile: 8 rows x 32 px (M=256) x 64 oc. Warp w = row w.
// A strip: 340 positions x 40 halves (stride 80B, 16B aligned).
// smem bytes: sAhi@0 (27200), sAlo@27200, W@54400 (hi buf0/1 @ +0/+5120,
//             lo @ +10240/+15360), sbias@74880. GSM=75264.
#define GSM 75264
template<int NCB, int MODE>
__global__ __launch_bounds__(256)
void gconv_kernel(const float* __restrict__ in, const __half* __restrict__ whi,
                  const __half* __restrict__ wlo, const float* __restrict__ bias,
                  int oc_total, int OCpad,
                  float* __restrict__ outf, float* __restrict__ outf2,
                  const float* __restrict__ flow)
{
    extern __shared__ char smem_[];
    __half* sAhi = (__half*)smem_;
    __half* sAlo = (__half*)(smem_ + 27200);
    __half* sWb  = (__half*)(smem_ + 54400);   // [buf][hi 2560][..], lo at +5120 halves
    float* sbias = (float*)(smem_ + 74880);

    const int tid = threadIdx.x;
    const int wid = tid >> 5, lane = tid & 31;
    const int h0 = (blockIdx.x >> 3) * 8;
    const int w00 = (blockIdx.x & 7) * 32;
    const int ocb = blockIdx.y * 64;
    const int CIN = NCB * 64;
    int nfb = (oc_total - ocb + 7) >> 3; if (nfb > 8) nfb = 8;

    const u32 sAhi_a = smem_u32(sAhi), sAlo_a = smem_u32(sAlo);
    const u32 sW_a   = smem_u32(sWb);

    if (tid < 64) sbias[tid] = (ocb + tid < oc_total) ? bias[ocb + tid] : 0.f;

    // W staging indices (per thread, constant)
    const int wo = tid >> 2, wq = (tid & 3) * 8;

    float acc0[8][4], acc1[8][4];
#pragma unroll
    for (int i = 0; i < 8; i++)
#pragma unroll
        for (int j = 0; j < 4; j++) { acc0[i][j] = 0.f; acc1[i][j] = 0.f; }

    // lane-derived ldmatrix address components
    const int a_dp = (lane & 7) + ((lane >> 3) & 1) * 8;   // position offset
    const int a_dc = (lane >> 4) * 8;                      // channel offset
    const int b_dn = (lane & 7) + ((lane >> 4) & 1) * 8;   // n offset
    const int b_dc = ((lane >> 3) & 1) * 8;                // k offset

    for (int cb = 0; cb < NCB; cb++)
    for (int hf = 0; hf < 2; hf++) {
        const int c0 = cb * 64 + hf * 32;
        __syncthreads();   // previous chunk's readers done with sA and W buf0
        // ---- stage strip interior: 10 rows x 32 cols x 32 ch ----
#pragma unroll
        for (int i = 0; i < 5; i++) {
            int j = tid + i * 256;
            int rr = j >> 7, rem = j & 127;
            int cp = rem >> 3, q = rem & 7;
            int gh = h0 - 1 + rr;
            int c = cp * 2;
            float4 va = make_float4(0.f, 0.f, 0.f, 0.f), vb = va;
            if ((unsigned)gh < Hd) {
                const float* p = in + (size_t)(c0 + c) * HW + gh * Wd + (w00 + q * 4);
                va = *(const float4*)p;
                vb = *(const float4*)(p + HW);
            }
            float av[4] = {va.x, va.y, va.z, va.w};
            float bv[4] = {vb.x, vb.y, vb.z, vb.w};
            int ptb = rr * 34 + 1 + q * 4;
#pragma unroll
            for (int k = 0; k < 4; k++) {
                __half ha = __float2half_rn(av[k]), hb = __float2half_rn(bv[k]);
                __half la = __float2half_rn(av[k] - __half2float(ha));
                __half lb = __float2half_rn(bv[k] - __half2float(hb));
                *(__half2*)&sAhi[(ptb + k) * 40 + c] = __halves2half2(ha, hb);
                *(__half2*)&sAlo[(ptb + k) * 40 + c] = __halves2half2(la, lb);
            }
        }
        // ---- edges s=0, s=33 ----
#pragma unroll
        for (int i = 0; i < 2; i++) {
            int j = tid + i * 256;
            if (j < 320) {
                int rr = j >> 5, rem = j & 31;
                int cp = rem >> 1, e = rem & 1;
                int s = e ? 33 : 0;
                int gh = h0 - 1 + rr, gw = w00 - 1 + s;
                int c = cp * 2;
                float v0 = 0.f, v1 = 0.f;
                if ((unsigned)gh < Hd && (unsigned)gw < Wd) {
                    const float* p = in + (size_t)(c0 + c) * HW + gh * Wd + gw;
                    v0 = p[0]; v1 = p[HW];
                }
                __half h0v = __float2half_rn(v0), h1v = __float2half_rn(v1);
                __half l0v = __float2half_rn(v0 - __half2float(h0v));
                __half l1v = __float2half_rn(v1 - __half2float(h1v));
                int pt = rr * 34 + s;
                *(__half2*)&sAhi[pt * 40 + c] = __halves2half2(h0v, h1v);
                *(__half2*)&sAlo[pt * 40 + c] = __halves2half2(l0v, l1v);
            }
        }
        // ---- stage W tap0 into buf0 (buf0 free: prev chunk's last tap used buf0
        //      but sync above ordered those reads before these writes) ----
        {
            size_t gi = (size_t)(0 * OCpad + ocb + wo) * CIN + c0 + wq;
            *(uint4*)&sWb[0 * 2560 + wo * 40 + wq]    = *(const uint4*)&whi[gi];
            *(uint4*)&sWb[10240/2 + 0 * 2560 + wo * 40 + wq] = *(const uint4*)&wlo[gi];
        }

        for (int tap = 0; tap < 9; tap++) {
            __syncthreads();   // W[tap] visible; prev compute done with buf[tap+1&1]
            const int buf = tap & 1;
            if (tap < 8) {
                const int nb = (tap + 1) & 1;
                size_t gi = (size_t)((tap + 1) * OCpad + ocb + wo) * CIN + c0 + wq;
                *(uint4*)&sWb[nb * 2560 + wo * 40 + wq]       = *(const uint4*)&whi[gi];
                *(uint4*)&sWb[5120 + nb * 2560 + wo * 40 + wq] = *(const uint4*)&wlo[gi];
            }
            const u32 whi_a = sW_a + buf * 5120;
            const u32 wlo_a = whi_a + 10240;
            const int pb0 = (tap / 3 + wid) * 34 + (tap % 3);
#pragma unroll
            for (int ks = 0; ks < 2; ks++) {
                const int kc = ks * 16;
                const int ch = kc + a_dc;
                u32 ah0[4], al0[4], ah1[4], al1[4];
                ldsm4(ah0, sAhi_a + ((pb0 + a_dp) * 40 + ch) * 2);
                ldsm4(al0, sAlo_a + ((pb0 + a_dp) * 40 + ch) * 2);
                ldsm4(ah1, sAhi_a + ((pb0 + 16 + a_dp) * 40 + ch) * 2);
                ldsm4(al1, sAlo_a + ((pb0 + 16 + a_dp) * 40 + ch) * 2);
#pragma unroll
                for (int pr = 0; pr < 4; pr++) {
                    if (pr * 2 < nfb) {
                        const int n = pr * 16 + b_dn;
                        const u32 wo32 = (n * 40 + kc + b_dc) * 2;
                        u32 bh[4], bl[4];
                        ldsm4(bh, whi_a + wo32);
                        ldsm4(bl, wlo_a + wo32);
                        const int nf = pr * 2;
                        mma16816(acc0[nf], ah0, bh[0], bh[1]);
                        mma16816(acc0[nf], al0, bh[0], bh[1]);
                        mma16816(acc0[nf], ah0, bl[0], bl[1]);
                        mma16816(acc1[nf], ah1, bh[0], bh[1]);
                        mma16816(acc1[nf], al1, bh[0], bh[1]);
                        mma16816(acc1[nf], ah1, bl[0], bl[1]);
                        if (nf + 1 < nfb) {
                            mma16816(acc0[nf+1], ah0, bh[2], bh[3]);
                            mma16816(acc0[nf+1], al0, bh[2], bh[3]);
                            mma16816(acc0[nf+1], ah0, bl[2], bl[3]);
                            mma16816(acc1[nf+1], ah1, bh[2], bh[3]);
                            mma16816(acc1[nf+1], al1, bh[2], bh[3]);
                            mma16816(acc1[nf+1], ah1, bl[2], bl[3]);
                        }
                    }
                }
            }
        }
    }

    // ---- epilogue: warp w = row h0+w; slab0 cols 0-15, slab1 cols 16-31 ----
    const int row = h0 + wid;
    const int pbase = row * Wd + w00 + (lane >> 2);
    const int ocl = (lane & 3) * 2;
#pragma unroll
    for (int nf = 0; nf < 8; nf++) {
        if (nf >= nfb) break;
        const int oc = ocb + nf * 8 + ocl;
        const float b0 = sbias[nf * 8 + ocl], b1 = sbias[nf * 8 + ocl + 1];
#pragma unroll
        for (int sl = 0; sl < 2; sl++) {
            const float* a = sl ? acc1[nf] : acc0[nf];
            const int pb = pbase + sl * 16;
            float v[4] = {a[0] + b0, a[1] + b1, a[2] + b0, a[3] + b1};
            const int ocs[4] = {oc, oc + 1, oc, oc + 1};
            const int pxs[4] = {pb, pb, pb + 8, pb + 8};
#pragma unroll
            for (int t = 0; t < 4; t++) {
                float r = v[t];
                const int o2 = ocs[t], px = pxs[t];
                if (MODE == 0) {
                    outf[(size_t)o2 * HW + px] = (r >= 0.f) ? r : 0.1f * r;
                } else if (MODE == 1) {
                    outf[(size_t)o2 * HW + px] = r;
                } else {
                    if (o2 < 144) {
                        outf[(size_t)o2 * HW + px] =
                            10.0f * tanhf(r) + flow[((size_t)((o2 & 1) ^ 1)) * HW + px];
                    } else if (o2 < 216) {
                        outf2[(size_t)(o2 - 144) * HW + px] = 1.0f / (1.0f + expf(-r));
                    }
                }
            }
        }
    }
}

// ---------------- mdcn: fp16 NHWC gather + HMMA GEMM (unchanged) ----------------
__global__ __launch_bounds__(256)
void mdcn_kernel(const __half* __restrict__ xt, const float* __restrict__ off,
                 const float* __restrict__ mask, const __half* __restrict__ dwhi,
                 const __half* __restrict__ dwlo, const float* __restrict__ bias,
                 float* __restrict__ out)
{
    __shared__ __align__(16) __half sShi[64 * 90], sSlo[64 * 90];
    __shared__ __align__(16) __half sWhi[64 * 88], sWlo[64 * 88];
    __shared__ float sbias[64];
    const int tid = threadIdx.x;
    const int wid = tid >> 5, lane = tid & 31;
    const int h = blockIdx.y;
    const int col0 = blockIdx.x * 64;
    const int px = tid & 63;
    const int part = tid >> 6;
    const int pixg = col0 + px;
    const int hw = h * Wd + pixg;
    const int k_beg = (part == 0) ? 0 : 1 + part * 2;
    const int k_end = (part == 0) ? 3 : 3 + part * 2;

    if (tid < 64) sbias[tid] = bias[tid];
    for (int i = tid; i < 64 * 8; i += 256) {
        int p = i >> 3, j = i & 7;
        sShi[p * 90 + 72 + j] = __ushort_as_half(0);
        sSlo[p * 90 + 72 + j] = __ushort_as_half(0);
    }

    float acc[8][4];
#pragma unroll
    for (int i = 0; i < 8; i++)
#pragma unroll
        for (int j = 0; j < 4; j++) acc[i][j] = 0.f;

    for (int g = 0; g < 8; g++) {
        __syncthreads();
        {
            const u32* gh32 = (const u32*)(dwhi + g * 5632);
            const u32* gl32 = (const u32*)(dwlo + g * 5632);
            for (int i = tid; i < 2816; i += 256) {
                ((u32*)sWhi)[i] = gh32[i];
                ((u32*)sWlo)[i] = gl32[i];
            }
        }
        for (int k = k_beg; k < k_end; k++) {
            int gk = g * 9 + k;
            float offy = off[(gk * 2 + 0) * HW + hw];
            float offx = off[(gk * 2 + 1) * HW + hw];
            float m    = mask[gk * HW + hw];
            float py = (float)h    + (float)(k / 3 - 1) + offy;
            float pxf = (float)pixg + (float)(k % 3 - 1) + offx;
            float y0f = floorf(py), x0f = floorf(pxf);
            float ly = py - y0f, lx = pxf - x0f;
            int y0 = (int)y0f, x0i = (int)x0f;
            int y1 = y0 + 1,  x1 = x0i + 1;
            bool vy0 = (unsigned)y0 < Hd, vy1 = (unsigned)y1 < Hd;
            bool vx0 = (unsigned)x0i < Wd, vx1 = (unsigned)x1 < Wd;
            int yc0 = min(max(y0, 0), Hd - 1), yc1 = min(max(y1, 0), Hd - 1);
            int xc0 = min(max(x0i, 0), Wd - 1), xc1 = min(max(x1, 0), Wd - 1);
            float w00 = (vy0 && vx0) ? (1.f - ly) * (1.f - lx) * m : 0.f;
            float w01 = (vy0 && vx1) ? (1.f - ly) * lx * m : 0.f;
            float w10 = (vy1 && vx0) ? ly * (1.f - lx) * m : 0.f;
            float w11 = (vy1 && vx1) ? ly * lx * m : 0.f;
            uint4 r00 = *(const uint4*)(xt + ((size_t)(yc0 * Wd + xc0)) * 64 + g * 8);
            uint4 r01 = *(const uint4*)(xt + ((size_t)(yc0 * Wd + xc1)) * 64 + g * 8);
            uint4 r10 = *(const uint4*)(xt + ((size_t)(yc1 * Wd + xc0)) * 64 + g * 8);
            uint4 r11 = *(const uint4*)(xt + ((size_t)(yc1 * Wd + xc1)) * 64 + g * 8);
            const __half2* hA = (const __half2*)&r00;
            const __half2* hB = (const __half2*)&r01;
            const __half2* hC = (const __half2*)&r10;
            const __half2* hD = (const __half2*)&r11;
#pragma unroll
            for (int cc = 0; cc < 4; cc++) {
                float2 fa = __half22float2(hA[cc]);
                float2 fb = __half22float2(hB[cc]);
                float2 fc = __half22float2(hC[cc]);
                float2 fd = __half22float2(hD[cc]);
                float s0 = w00 * fa.x + w01 * fb.x + w10 * fc.x + w11 * fd.x;
                float s1 = w00 * fa.y + w01 * fb.y + w10 * fc.y + w11 * fd.y;
                __half h0 = __float2half_rn(s0), h1 = __float2half_rn(s1);
                sShi[px * 90 + (cc * 2 + 0) * 9 + k] = h0;
                sShi[px * 90 + (cc * 2 + 1) * 9 + k] = h1;
                sSlo[px * 90 + (cc * 2 + 0) * 9 + k] = __float2half_rn(s0 - __half2float(h0));
                sSlo[px * 90 + (cc * 2 + 1) * 9 + k] = __float2half_rn(s1 - __half2float(h1));
            }
        }
        __syncthreads();
        const int mw = wid & 3;
        const int nhalf = (wid >> 2) * 4;
        const int r = mw * 16 + (lane >> 2);
#pragma unroll
        for (int ks = 0; ks < 5; ks++) {
            const int kc = ks * 16 + (lane & 3) * 2;
            u32 ah[4], al[4];
            ah[0] = *(const u32*)&sShi[r * 90 + kc];
            ah[1] = *(const u32*)&sShi[(r + 8) * 90 + kc];
            ah[2] = *(const u32*)&sShi[r * 90 + kc + 8];
            ah[3] = *(const u32*)&sShi[(r + 8) * 90 + kc + 8];
            al[0] = *(const u32*)&sSlo[r * 90 + kc];
            al[1] = *(const u32*)&sSlo[(r + 8) * 90 + kc];
            al[2] = *(const u32*)&sSlo[r * 90 + kc + 8];
            al[3] = *(const u32*)&sSlo[(r + 8) * 90 + kc + 8];
#pragma unroll
            for (int nf = 0; nf < 4; nf++) {
                const int n = (nhalf + nf) * 8 + (lane >> 2);
                u32 bh0 = *(const u32*)&sWhi[n * 88 + kc];
                u32 bh1 = *(const u32*)&sWhi[n * 88 + kc + 8];
                u32 bl0 = *(const u32*)&sWlo[n * 88 + kc];
                u32 bl1 = *(const u32*)&sWlo[n * 88 + kc + 8];
                mma16816(acc[nf], ah, bh0, bh1);
                mma16816(acc[nf], al, bh0, bh1);
                mma16816(acc[nf], ah, bl0, bl1);
            }
        }
    }
    const int mw = wid & 3, nhalf = (wid >> 2) * 4;
    const int p1 = col0 + mw * 16 + (lane >> 2);
    const int p2 = p1 + 8;
    const int oc0 = (lane & 3) * 2;
#pragma unroll
    for (int nf = 0; nf < 4; nf++) {
        const int oc = (nhalf + nf) * 8 + oc0;
        out[(size_t)oc * HW + h * Wd + p1]       = acc[nf][0] + sbias[oc];
        out[(size_t)(oc + 1) * HW + h * Wd + p1] = acc[nf][1] + sbias[oc + 1];
        out[(size_t)oc * HW + h * Wd + p2]       = acc[nf][2] + sbias[oc];
        out[(size_t)(oc + 1) * HW + h * Wd + p2] = acc[nf][3] + sbias[oc + 1];
    }
}

// ---------------- host orchestration ----------------
extern "C" void kernel_launch(void* const* d_in, const int* in_sizes, int n_in,
                              void* d_out, int out_size)
{
    const float* feat_prev       = (const float*)d_in[0];
    const float* feat_next       = (const float*)d_in[1];
    const float* extra_feat_prev = (const float*)d_in[2];
    const float* extra_feat_next = (const float*)d_in[3];
    const float* flow_prev       = (const float*)d_in[4];
    const float* flow_next       = (const float*)d_in[5];
    const float* o1b[4] = {(const float*)d_in[7],  (const float*)d_in[9],
                           (const float*)d_in[11], (const float*)d_in[13]};
    const float* o2b[4] = {(const float*)d_in[15], (const float*)d_in[17],
                           (const float*)d_in[19], (const float*)d_in[21]};
    const float* dcn1_w = (const float*)d_in[22];
    const float* dcn1_b = (const float*)d_in[23];
    const float* dcn2_w = (const float*)d_in[24];
    const float* dcn2_b = (const float*)d_in[25];
    const float* fus_b  = (const float*)d_in[27];
    float* out = (float*)d_out;

    float *ba, *bb, *offp, *maskp, *catp;
    __half *xt, *whi, *wlo, *dwhi, *dwlo;
    cudaGetSymbolAddress((void**)&ba, g_buf_a);
    cudaGetSymbolAddress((void**)&bb, g_buf_b);
    cudaGetSymbolAddress((void**)&offp,  g_off);
    cudaGetSymbolAddress((void**)&maskp, g_mask);
    cudaGetSymbolAddress((void**)&catp,  g_cat);
    cudaGetSymbolAddress((void**)&xt,    g_xt);
    cudaGetSymbolAddress((void**)&whi, g_whi);
    cudaGetSymbolAddress((void**)&wlo, g_wlo);
    cudaGetSymbolAddress((void**)&dwhi, g_dwhi);
    cudaGetSymbolAddress((void**)&dwlo, g_dwlo);

    cudaFuncSetAttribute(gconv_kernel<2,0>, cudaFuncAttributeMaxDynamicSharedMemorySize, GSM);
    cudaFuncSetAttribute(gconv_kernel<1,0>, cudaFuncAttributeMaxDynamicSharedMemorySize, GSM);
    cudaFuncSetAttribute(gconv_kernel<1,2>, cudaFuncAttributeMaxDynamicSharedMemorySize, GSM);
    cudaFuncSetAttribute(gconv_kernel<2,1>, cudaFuncAttributeMaxDynamicSharedMemorySize, GSM);

    WSrc ws;
    ws.p[0] = (const float*)d_in[6];  ws.p[1] = (const float*)d_in[8];
    ws.p[2] = (const float*)d_in[10]; ws.p[3] = (const float*)d_in[12];
    ws.p[4] = (const float*)d_in[14]; ws.p[5] = (const float*)d_in[16];
    ws.p[6] = (const float*)d_in[18]; ws.p[7] = (const float*)d_in[20];
    ws.p[8] = (const float*)d_in[26];
    wprep_all<<<(663552 + 255) / 256, 256>>>(ws, whi, wlo);
    dcnprep_all<<<dim3(176, 2), 256>>>(dcn1_w, dcn2_w, dwhi, dwlo);
    tohwc_kernel<<<512, 128>>>(feat_prev, xt);

    dim3 g1(256, 1), g4(256, 4), mg(4, 256);

    gconv_kernel<2,0><<<g1, 256, GSM>>>(extra_feat_prev, whi + 0, wlo + 0, o1b[0], 64, 64, ba, nullptr, nullptr);
    gconv_kernel<1,0><<<g1, 256, GSM>>>(ba, whi + 73728, wlo + 73728, o1b[1], 64, 64, bb, nullptr, nullptr);
    gconv_kernel<1,0><<<g1, 256, GSM>>>(bb, whi + 110592, wlo + 110592, o1b[2], 64, 64, ba, nullptr, nullptr);
    gconv_kernel<1,2><<<g4, 256, GSM>>>(ba, whi + 147456, wlo + 147456, o1b[3], 216, 256, offp, maskp, flow_prev);
    mdcn_kernel<<<mg, 256>>>(xt, offp, maskp, dwhi, dwlo, dcn1_b, catp);

    gconv_kernel<2,0><<<g1, 256, GSM>>>(extra_feat_next, whi + 294912, wlo + 294912, o2b[0], 64, 64, ba, nullptr, nullptr);
    gconv_kernel<1,0><<<g1, 256, GSM>>>(ba, whi + 368640, wlo + 368640, o2b[1], 64, 64, bb, nullptr, nullptr);
    gconv_kernel<1,0><<<g1, 256, GSM>>>(bb, whi + 405504, wlo + 405504, o2b[2], 64, 64, ba, nullptr, nullptr);
    gconv_kernel<1,2><<<g4, 256, GSM>>>(ba, whi + 442368, wlo + 442368, o2b[3], 216, 256, offp, maskp, flow_next);
    tohwc_kernel<<<512, 128>>>(feat_next, xt);
    mdcn_kernel<<<mg, 256>>>(xt, offp, maskp, dwhi + 45056, dwlo + 45056, dcn2_b, catp + (size_t)64 * HW);

    gconv_kernel<2,1><<<g1, 256, GSM>>>(catp, whi + 589824, wlo + 589824, fus_b, 64, 64, out, nullptr, nullptr);
}

// round 14
// speedup vs baseline: 5.3215x; 1.0094x over previous
#include <cuda_runtime.h>
#include <cuda_fp16.h>
#include <math.h>

#define Wd 256
#define Hd 256
#define HW 65536
typedef unsigned int u32;

// ---------------- scratch (no allocation allowed) ----------------
__device__ float g_off [144 * HW];
__device__ float g_mask[ 72 * HW];
__device__ float g_cat [128 * HW];
__device__ __align__(16) __half g_xt[64 * HW];              // NHWC feat, fp16
__device__ __align__(16) __half g_ahi_a[HW * 64];           // act ping hi
__device__ __align__(16) __half g_alo_a[HW * 64];
__device__ __align__(16) __half g_ahi_b[HW * 64];           // act pong hi
__device__ __align__(16) __half g_alo_b[HW * 64];
__device__ __align__(16) __half g_whi[663552];
__device__ __align__(16) __half g_wlo[663552];
__device__ __align__(16) __half g_dwhi[2 * 45056];
__device__ __align__(16) __half g_dwlo[2 * 45056];

// ---------------- merged conv-weight pre-convert ----------------
struct WSrc { const float* p[9]; };
__global__ void wprep_all(WSrc ws, __half* __restrict__ dhi, __half* __restrict__ dlo)
{
    const int off[9]  = {0,73728,110592,147456,294912,368640,405504,442368,589824};
    const int CINs[9] = {128,64,64,64,128,64,64,64,128};
    const int OCs[9]  = {64,64,64,216,64,64,64,216,64};
    const int OCp[9]  = {64,64,64,256,64,64,64,256,64};
    int idx = blockIdx.x * 256 + threadIdx.x;
    if (idx >= 663552) return;
    int seg = 0;
#pragma unroll
    for (int s = 1; s < 9; s++) if (idx >= off[s]) seg = s;
    int r = idx - off[seg];
    int per_t = OCp[seg] * CINs[seg];
    int t = r / per_t; r -= t * per_t;
    int o = r / CINs[seg], c = r - o * CINs[seg];
    float w = (o < OCs[seg]) ? ws.p[seg][(o * CINs[seg] + c) * 9 + t] : 0.f;
    __half h = __float2half_rn(w);
    dhi[idx] = h;
    dlo[idx] = __float2half_rn(w - __half2float(h));
}

// ---------------- dcn weight pre-convert ----------------
__global__ void dcnprep_all(const float* __restrict__ s1, const float* __restrict__ s2,
                            __half* __restrict__ dhi, __half* __restrict__ dlo)
{
    int idx = blockIdx.x * 256 + threadIdx.x;
    if (idx >= 45056) return;
    const float* src = blockIdx.y ? s2 : s1;
    int base = blockIdx.y * 45056;
    int g = idx / 5632, r = idx - g * 5632, o = r / 88, ck = r - o * 88;
    float w = 0.f;
    if (ck < 72) { int c = ck / 9, k = ck - c * 9; w = src[((size_t)o * 64 + g * 8 + c) * 9 + k]; }
    __half h = __float2half_rn(w);
    dhi[base + idx] = h;
    dlo[base + idx] = __float2half_rn(w - __half2float(h));
}

// ---------------- NCHW fp32 -> NHWC fp16 (feat for mdcn) ----------------
__global__ __launch_bounds__(128)
void tohwc_kernel(const float* __restrict__ src, __half* __restrict__ dst)
{
    __shared__ float s[64 * 130];
    const int t = threadIdx.x;
    const int pix0 = blockIdx.x * 128;
    for (int c = 0; c < 64; c++) s[c * 130 + t] = src[(size_t)c * HW + pix0 + t];
    __syncthreads();
    for (int i = 0; i < 64; i++) {
        int L = t + i * 128;
        dst[(size_t)pix0 * 64 + L] = __float2half_rn(s[(L & 63) * 130 + (L >> 6)]);
    }
}

__device__ __forceinline__ void mma16816(float* d, const u32* a, u32 b0, u32 b1) {
    asm volatile(
        "mma.sync.aligned.m16n8k16.row.col.f32.f16.f16.f32 "
        "{%0,%1,%2,%3}, {%4,%5,%6,%7}, {%8,%9}, {%0,%1,%2,%3};"
        : "+f"(d[0]), "+f"(d[1]), "+f"(d[2]), "+f"(d[3])
        : "r"(a[0]), "r"(a[1]), "r"(a[2]), "r"(a[3]), "r"(b0), "r"(b1));
}
__device__ __forceinline__ void ldsm4(u32* r, u32 addr) {
    asm volatile("ldmatrix.sync.aligned.m8n8.x4.shared.b16 {%0,%1,%2,%3}, [%4];"
                 : "=r"(r[0]), "=r"(r[1]), "=r"(r[2]), "=r"(r[3]) : "r"(addr));
}
__device__ __forceinline__ u32 smem_u32(const void* p) {
    return (u32)__cvta_generic_to_shared(p);
}
__device__ __forceinline__ void cp_async16(void* dst, const void* src, int sb) {
    asm volatile("cp.async.cg.shared.global [%0], [%1], 16, %2;\n"
                 :: "r"(smem_u32(dst)), "l"(src), "r"(sb) : "memory");
}
__device__ __forceinline__ void cp_commit() {
    asm volatile("cp.async.commit_group;\n" ::: "memory");
}
template<int N>
__device__ __forceinline__ void cp_wait() {
    asm volatile("cp.async.wait_group %0;\n" :: "n"(N) : "memory");
}

// ---------------- HMMA implicit-GEMM 3x3 conv ----------------
// 256 thr (8 warps). Tile: 8 rows x 32 px (M=256) x 64 oc. Warp w = row w.
// A strip: 340 positions x 40 halves (stride 80B). W double-buffered.
// INFMT: 0 = fp32 NCHW input, 1 = fp16 hi/lo NHWC input (cp.async staging).
// MODE:  0 = lrelu -> hi/lo NHWC out; 1 = plain -> fp32 NCHW; 2 = offxform.
#define GSM 75264
template<int NCB, int MODE, int INFMT>
__global__ __launch_bounds__(256)
void gconv_kernel(const float* __restrict__ in,
                  const __half* __restrict__ inhi, const __half* __restrict__ inlo,
                  const __half* __restrict__ whi, const __half* __restrict__ wlo,
                  const float* __restrict__ bias, int oc_total, int OCpad,
                  float* __restrict__ outf, float* __restrict__ outf2,
                  const float* __restrict__ flow,
                  __half* __restrict__ outhi, __half* __restrict__ outlo)
{
    extern __shared__ char smem_[];
    __half* sAhi = (__half*)smem_;
    __half* sAlo = (__half*)(smem_ + 27200);
    __half* sWb  = (__half*)(smem_ + 54400);
    float* sbias = (float*)(smem_ + 74880);

    const int tid = threadIdx.x;
    const int wid = tid >> 5, lane = tid & 31;
    const int h0 = (blockIdx.x >> 3) * 8;
    const int w00 = (blockIdx.x & 7) * 32;
    const int ocb = blockIdx.y * 64;
    const int CIN = NCB * 64;
    int nfb = (oc_total - ocb + 7) >> 3; if (nfb > 8) nfb = 8;

    const u32 sAhi_a = smem_u32(sAhi), sAlo_a = smem_u32(sAlo);
    const u32 sW_a   = smem_u32(sWb);

    if (tid < 64) sbias[tid] = (ocb + tid < oc_total) ? bias[ocb + tid] : 0.f;

    const int wo = tid >> 2, wq = (tid & 3) * 8;

    float acc0[8][4], acc1[8][4];
#pragma unroll
    for (int i = 0; i < 8; i++)
#pragma unroll
        for (int j = 0; j < 4; j++) { acc0[i][j] = 0.f; acc1[i][j] = 0.f; }

    const int a_dp = (lane & 7) + ((lane >> 3) & 1) * 8;
    const int a_dc = (lane >> 4) * 8;
    const int b_dn = (lane & 7) + ((lane >> 4) & 1) * 8;
    const int b_dc = ((lane >> 3) & 1) * 8;

    for (int cb = 0; cb < NCB; cb++)
    for (int hf = 0; hf < 2; hf++) {
        const int c0 = cb * 64 + hf * 32;
        __syncthreads();
        if (INFMT == 0) {
            // ---- fp32 NCHW staging (layer1 / fusion) ----
#pragma unroll
            for (int i = 0; i < 5; i++) {
                int j = tid + i * 256;
                int rr = j >> 7, rem = j & 127;
                int cp = rem >> 3, q = rem & 7;
                int gh = h0 - 1 + rr;
                int c = cp * 2;
                float4 va = make_float4(0.f, 0.f, 0.f, 0.f), vb = va;
                if ((unsigned)gh < Hd) {
                    const float* p = in + (size_t)(c0 + c) * HW + gh * Wd + (w00 + q * 4);
                    va = *(const float4*)p;
                    vb = *(const float4*)(p + HW);
                }
                float av[4] = {va.x, va.y, va.z, va.w};
                float bv[4] = {vb.x, vb.y, vb.z, vb.w};
                int ptb = rr * 34 + 1 + q * 4;
#pragma unroll
                for (int k = 0; k < 4; k++) {
                    __half ha = __float2half_rn(av[k]), hb = __float2half_rn(bv[k]);
                    __half la = __float2half_rn(av[k] - __half2float(ha));
                    __half lb = __float2half_rn(bv[k] - __half2float(hb));
                    *(__half2*)&sAhi[(ptb + k) * 40 + c] = __halves2half2(ha, hb);
                    *(__half2*)&sAlo[(ptb + k) * 40 + c] = __halves2half2(la, lb);
                }
            }
#pragma unroll
            for (int i = 0; i < 2; i++) {
                int j = tid + i * 256;
                if (j < 320) {
                    int rr = j >> 5, rem = j & 31;
                    int cp = rem >> 1, e = rem & 1;
                    int s = e ? 33 : 0;
                    int gh = h0 - 1 + rr, gw = w00 - 1 + s;
                    int c = cp * 2;
                    float v0 = 0.f, v1 = 0.f;
                    if ((unsigned)gh < Hd && (unsigned)gw < Wd) {
                        const float* p = in + (size_t)(c0 + c) * HW + gh * Wd + gw;
                        v0 = p[0]; v1 = p[HW];
                    }
                    __half h0v = __float2half_rn(v0), h1v = __float2half_rn(v1);
                    __half l0v = __float2half_rn(v0 - __half2float(h0v));
                    __half l1v = __float2half_rn(v1 - __half2float(h1v));
                    int pt = rr * 34 + s;
                    *(__half2*)&sAhi[pt * 40 + c] = __halves2half2(h0v, h1v);
                    *(__half2*)&sAlo[pt * 40 + c] = __halves2half2(l0v, l1v);
                }
            }
        } else {
            // ---- fp16 hi/lo NHWC staging: pure cp.async, zero reg traffic ----
            // 340 positions x 4 quads x 2 planes = 2720 16B copies
#pragma unroll
            for (int i = 0; i < 11; i++) {
                int j = tid + i * 256;
                if (j < 2720) {
                    int plane = (j >= 1360) ? 1 : 0;
                    int jj = j - plane * 1360;
                    int p = jj >> 2, q = jj & 3;
                    int rr = p / 34, s = p - rr * 34;
                    int gh = h0 - 1 + rr, gw = w00 - 1 + s;
                    bool v = ((unsigned)gh < Hd) && ((unsigned)gw < Wd);
                    const __half* base = plane ? inlo : inhi;
                    const __half* src = v ? (base + ((size_t)(gh * Wd + gw)) * 64 + c0 + q * 8)
                                          : base;
                    __half* dst = (plane ? sAlo : sAhi) + p * 40 + q * 8;
                    cp_async16(dst, src, v ? 16 : 0);
                }
            }
            cp_commit();
            cp_wait<0>();
        }
        // ---- stage W tap0 into buf0 ----
        {
            size_t gi = (size_t)(0 * OCpad + ocb + wo) * CIN + c0 + wq;
            *(uint4*)&sWb[0 * 2560 + wo * 40 + wq]        = *(const uint4*)&whi[gi];
            *(uint4*)&sWb[5120 + 0 * 2560 + wo * 40 + wq] = *(const uint4*)&wlo[gi];
        }

        for (int tap = 0; tap < 9; tap++) {
            __syncthreads();
            const int buf = tap & 1;
            if (tap < 8) {
                const int nb = (tap + 1) & 1;
                size_t gi = (size_t)((tap + 1) * OCpad + ocb + wo) * CIN + c0 + wq;
                *(uint4*)&sWb[nb * 2560 + wo * 40 + wq]        = *(const uint4*)&whi[gi];
                *(uint4*)&sWb[5120 + nb * 2560 + wo * 40 + wq] = *(const uint4*)&wlo[gi];
            }
            const u32 whi_a = sW_a + buf * 5120;
            const u32 wlo_a = whi_a + 10240;
            const int pb0 = (tap / 3 + wid) * 34 + (tap % 3);
#pragma unroll
            for (int ks = 0; ks < 2; ks++) {
                const int kc = ks * 16;
                const int ch = kc + a_dc;
                u32 ah0[4], al0[4], ah1[4], al1[4];
                ldsm4(ah0, sAhi_a + ((pb0 + a_dp) * 40 + ch) * 2);
                ldsm4(al0, sAlo_a + ((pb0 + a_dp) * 40 + ch) * 2);
                ldsm4(ah1, sAhi_a + ((pb0 + 16 + a_dp) * 40 + ch) * 2);
                ldsm4(al1, sAlo_a + ((pb0 + 16 + a_dp) * 40 + ch) * 2);
#pragma unroll
                for (int pr = 0; pr < 4; pr++) {
                    if (pr * 2 < nfb) {
                        const int n = pr * 16 + b_dn;
                        const u32 wo32 = (n * 40 + kc + b_dc) * 2;
                        u32 bh[4], bl[4];
                        ldsm4(bh, whi_a + wo32);
                        ldsm4(bl, wlo_a + wo32);
                        const int nf = pr * 2;
                        mma16816(acc0[nf], ah0, bh[0], bh[1]);
                        mma16816(acc0[nf], al0, bh[0], bh[1]);
                        mma16816(acc0[nf], ah0, bl[0], bl[1]);
                        mma16816(acc1[nf], ah1, bh[0], bh[1]);
                        mma16816(acc1[nf], al1, bh[0], bh[1]);
                        mma16816(acc1[nf], ah1, bl[0], bl[1]);
                        if (nf + 1 < nfb) {
                            mma16816(acc0[nf+1], ah0, bh[2], bh[3]);
                            mma16816(acc0[nf+1], al0, bh[2], bh[3]);
                            mma16816(acc0[nf+1], ah0, bl[2], bl[3]);
                            mma16816(acc1[nf+1], ah1, bh[2], bh[3]);
                            mma16816(acc1[nf+1], al1, bh[2], bh[3]);
                            mma16816(acc1[nf+1], ah1, bl[2], bl[3]);
                        }
                    }
                }
            }
        }
    }

    // ---- epilogue ----
    const int row = h0 + wid;
    const int pcol = w00 + (lane >> 2);
    const int ocl = (lane & 3) * 2;
#pragma unroll
    for (int nf = 0; nf < 8; nf++) {
        if (nf >= nfb) break;
        const int oc = ocb + nf * 8 + ocl;
        const float b0 = sbias[nf * 8 + ocl], b1 = sbias[nf * 8 + ocl + 1];
#pragma unroll
        for (int sl = 0; sl < 2; sl++) {
            const float* a = sl ? acc1[nf] : acc0[nf];
#pragma unroll
            for (int half_ = 0; half_ < 2; half_++) {
                const int px = row * Wd + pcol + sl * 16 + half_ * 8;
                float r0 = a[half_ * 2 + 0] + b0;
                float r1 = a[half_ * 2 + 1] + b1;
                if (MODE == 0) {
                    r0 = (r0 >= 0.f) ? r0 : 0.1f * r0;
                    r1 = (r1 >= 0.f) ? r1 : 0.1f * r1;
                    __half h0v = __float2half_rn(r0), h1v = __float2half_rn(r1);
                    __half l0v = __float2half_rn(r0 - __half2float(h0v));
                    __half l1v = __float2half_rn(r1 - __half2float(h1v));
                    *(__half2*)&outhi[(size_t)px * 64 + oc] = __halves2half2(h0v, h1v);
                    *(__half2*)&outlo[(size_t)px * 64 + oc] = __halves2half2(l0v, l1v);
                } else if (MODE == 1) {
                    outf[(size_t)oc * HW + px] = r0;
                    outf[(size_t)(oc + 1) * HW + px] = r1;
                } else {
                    float rr[2] = {r0, r1};
#pragma unroll
                    for (int t = 0; t < 2; t++) {
                        const int o2 = oc + t;
                        if (o2 < 144) {
                            outf[(size_t)o2 * HW + px] =
                                10.0f * tanhf(rr[t]) + flow[((size_t)((o2 & 1) ^ 1)) * HW + px];
                        } else if (o2 < 216) {
                            outf2[(size_t)(o2 - 144) * HW + px] = 1.0f / (1.0f + expf(-rr[t]));
                        }
                    }
                }
            }
        }
    }
}

// ---------------- mdcn: fp16 NHWC gather + HMMA GEMM (unchanged) ----------------
__global__ __launch_bounds__(256)
void mdcn_kernel(const __half* __restrict__ xt, const float* __restrict__ off,
                 const float* __restrict__ mask, const __half* __restrict__ dwhi,
                 const __half* __restrict__ dwlo, const float* __restrict__ bias,
                 float* __restrict__ out)
{
    __shared__ __align__(16) __half sShi[64 * 90], sSlo[64 * 90];
    __shared__ __align__(16) __half sWhi[64 * 88], sWlo[64 * 88];
    __shared__ float sbias[64];
    const int tid = threadIdx.x;
    const int wid = tid >> 5, lane = tid & 31;
    const int h = blockIdx.y;
    const int col0 = blockIdx.x * 64;
    const int px = tid & 63;
    const int part = tid >> 6;
    const int pixg = col0 + px;
    const int hw = h * Wd + pixg;
    const int k_beg = (part == 0) ? 0 : 1 + part * 2;
    const int k_end = (part == 0) ? 3 : 3 + part * 2;

    if (tid < 64) sbias[tid] = bias[tid];
    for (int i = tid; i < 64 * 8; i += 256) {
        int p = i >> 3, j = i & 7;
        sShi[p * 90 + 72 + j] = __ushort_as_half(0);
        sSlo[p * 90 + 72 + j] = __ushort_as_half(0);
    }

    float acc[8][4];
#pragma unroll
    for (int i = 0; i < 8; i++)
#pragma unroll
        for (int j = 0; j < 4; j++) acc[i][j] = 0.f;

    for (int g = 0; g < 8; g++) {
        __syncthreads();
        {
            const u32* gh32 = (const u32*)(dwhi + g * 5632);
            const u32* gl32 = (const u32*)(dwlo + g * 5632);
            for (int i = tid; i < 2816; i += 256) {
                ((u32*)sWhi)[i] = gh32[i];
                ((u32*)sWlo)[i] = gl32[i];
            }
        }
        for (int k = k_beg; k < k_end; k++) {
            int gk = g * 9 + k;
            float offy = off[(gk * 2 + 0) * HW + hw];
            float offx = off[(gk * 2 + 1) * HW + hw];
            float m    = mask[gk * HW + hw];
            float py = (float)h    + (float)(k / 3 - 1) + offy;
            float pxf = (float)pixg + (float)(k % 3 - 1) + offx;
            float y0f = floorf(py), x0f = floorf(pxf);
            float ly = py - y0f, lx = pxf - x0f;
            int y0 = (int)y0f, x0i = (int)x0f;
            int y1 = y0 + 1,  x1 = x0i + 1;
            bool vy0 = (unsigned)y0 < Hd, vy1 = (unsigned)y1 < Hd;
            bool vx0 = (unsigned)x0i < Wd, vx1 = (unsigned)x1 < Wd;
            int yc0 = min(max(y0, 0), Hd - 1), yc1 = min(max(y1, 0), Hd - 1);
            int xc0 = min(max(x0i, 0), Wd - 1), xc1 = min(max(x1, 0), Wd - 1);
            float w00 = (vy0 && vx0) ? (1.f - ly) * (1.f - lx) * m : 0.f;
            float w01 = (vy0 && vx1) ? (1.f - ly) * lx * m : 0.f;
            float w10 = (vy1 && vx0) ? ly * (1.f - lx) * m : 0.f;
            float w11 = (vy1 && vx1) ? ly * lx * m : 0.f;
            uint4 r00 = *(const uint4*)(xt + ((size_t)(yc0 * Wd + xc0)) * 64 + g * 8);
            uint4 r01 = *(const uint4*)(xt + ((size_t)(yc0 * Wd + xc1)) * 64 + g * 8);
            uint4 r10 = *(const uint4*)(xt + ((size_t)(yc1 * Wd + xc0)) * 64 + g * 8);
            uint4 r11 = *(const uint4*)(xt + ((size_t)(yc1 * Wd + xc1)) * 64 + g * 8);
            const __half2* hA = (const __half2*)&r00;
            const __half2* hB = (const __half2*)&r01;
            const __half2* hC = (const __half2*)&r10;
            const __half2* hD = (const __half2*)&r11;
#pragma unroll
            for (int cc = 0; cc < 4; cc++) {
                float2 fa = __half22float2(hA[cc]);
                float2 fb = __half22float2(hB[cc]);
                float2 fc = __half22float2(hC[cc]);
                float2 fd = __half22float2(hD[cc]);
                float s0 = w00 * fa.x + w01 * fb.x + w10 * fc.x + w11 * fd.x;
                float s1 = w00 * fa.y + w01 * fb.y + w10 * fc.y + w11 * fd.y;
                __half h0 = __float2half_rn(s0), h1 = __float2half_rn(s1);
                sShi[px * 90 + (cc * 2 + 0) * 9 + k] = h0;
                sShi[px * 90 + (cc * 2 + 1) * 9 + k] = h1;
                sSlo[px * 90 + (cc * 2 + 0) * 9 + k] = __float2half_rn(s0 - __half2float(h0));
                sSlo[px * 90 + (cc * 2 + 1) * 9 + k] = __float2half_rn(s1 - __half2float(h1));
            }
        }
        __syncthreads();
        const int mw = wid & 3;
        const int nhalf = (wid >> 2) * 4;
        const int r = mw * 16 + (lane >> 2);
#pragma unroll
        for (int ks = 0; ks < 5; ks++) {
            const int kc = ks * 16 + (lane & 3) * 2;
            u32 ah[4], al[4];
            ah[0] = *(const u32*)&sShi[r * 90 + kc];
            ah[1] = *(const u32*)&sShi[(r + 8) * 90 + kc];
            ah[2] = *(const u32*)&sShi[r * 90 + kc + 8];
            ah[3] = *(const u32*)&sShi[(r + 8) * 90 + kc + 8];
            al[0] = *(const u32*)&sSlo[r * 90 + kc];
            al[1] = *(const u32*)&sSlo[(r + 8) * 90 + kc];
            al[2] = *(const u32*)&sSlo[r * 90 + kc + 8];
            al[3] = *(const u32*)&sSlo[(r + 8) * 90 + kc + 8];
#pragma unroll
            for (int nf = 0; nf < 4; nf++) {
                const int n = (nhalf + nf) * 8 + (lane >> 2);
                u32 bh0 = *(const u32*)&sWhi[n * 88 + kc];
                u32 bh1 = *(const u32*)&sWhi[n * 88 + kc + 8];
                u32 bl0 = *(const u32*)&sWlo[n * 88 + kc];
                u32 bl1 = *(const u32*)&sWlo[n * 88 + kc + 8];
                mma16816(acc[nf], ah, bh0, bh1);
                mma16816(acc[nf], al, bh0, bh1);
                mma16816(acc[nf], ah, bl0, bl1);
            }
        }
    }
    const int mw = wid & 3, nhalf = (wid >> 2) * 4;
    const int p1 = col0 + mw * 16 + (lane >> 2);
    const int p2 = p1 + 8;
    const int oc0 = (lane & 3) * 2;
#pragma unroll
    for (int nf = 0; nf < 4; nf++) {
        const int oc = (nhalf + nf) * 8 + oc0;
        out[(size_t)oc * HW + h * Wd + p1]       = acc[nf][0] + sbias[oc];
        out[(size_t)(oc + 1) * HW + h * Wd + p1] = acc[nf][1] + sbias[oc + 1];
        out[(size_t)oc * HW + h * Wd + p2]       = acc[nf][2] + sbias[oc];
        out[(size_t)(oc + 1) * HW + h * Wd + p2] = acc[nf][3] + sbias[oc + 1];
    }
}

// ---------------- host orchestration ----------------
extern "C" void kernel_launch(void* const* d_in, const int* in_sizes, int n_in,
                              void* d_out, int out_size)
{
    const float* feat_prev       = (const float*)d_in[0];
    const float* feat_next       = (const float*)d_in[1];
    const float* extra_feat_prev = (const float*)d_in[2];
    const float* extra_feat_next = (const float*)d_in[3];
    const float* flow_prev       = (const float*)d_in[4];
    const float* flow_next       = (const float*)d_in[5];
    const float* o1b[4] = {(const float*)d_in[7],  (const float*)d_in[9],
                           (const float*)d_in[11], (const float*)d_in[13]};
    const float* o2b[4] = {(const float*)d_in[15], (const float*)d_in[17],
                           (const float*)d_in[19], (const float*)d_in[21]};
    const float* dcn1_w = (const float*)d_in[22];
    const float* dcn1_b = (const float*)d_in[23];
    const float* dcn2_w = (const float*)d_in[24];
    const float* dcn2_b = (const float*)d_in[25];
    const float* fus_b  = (const float*)d_in[27];
    float* out = (float*)d_out;

    float *offp, *maskp, *catp;
    __half *xt, *whi, *wlo, *dwhi, *dwlo, *ahiA, *aloA, *ahiB, *aloB;
    cudaGetSymbolAddress((void**)&offp,  g_off);
    cudaGetSymbolAddress((void**)&maskp, g_mask);
    cudaGetSymbolAddress((void**)&catp,  g_cat);
    cudaGetSymbolAddress((void**)&xt,    g_xt);
    cudaGetSymbolAddress((void**)&whi, g_whi);
    cudaGetSymbolAddress((void**)&wlo, g_wlo);
    cudaGetSymbolAddress((void**)&dwhi, g_dwhi);
    cudaGetSymbolAddress((void**)&dwlo, g_dwlo);
    cudaGetSymbolAddress((void**)&ahiA, g_ahi_a);
    cudaGetSymbolAddress((void**)&aloA, g_alo_a);
    cudaGetSymbolAddress((void**)&ahiB, g_ahi_b);
    cudaGetSymbolAddress((void**)&aloB, g_alo_b);

    cudaFuncSetAttribute(gconv_kernel<2,0,0>, cudaFuncAttributeMaxDynamicSharedMemorySize, GSM);
    cudaFuncSetAttribute(gconv_kernel<1,0,1>, cudaFuncAttributeMaxDynamicSharedMemorySize, GSM);
    cudaFuncSetAttribute(gconv_kernel<1,2,1>, cudaFuncAttributeMaxDynamicSharedMemorySize, GSM);
    cudaFuncSetAttribute(gconv_kernel<2,1,0>, cudaFuncAttributeMaxDynamicSharedMemorySize, GSM);

    WSrc ws;
    ws.p[0] = (const float*)d_in[6];  ws.p[1] = (const float*)d_in[8];
    ws.p[2] = (const float*)d_in[10]; ws.p[3] = (const float*)d_in[12];
    ws.p[4] = (const float*)d_in[14]; ws.p[5] = (const float*)d_in[16];
    ws.p[6] = (const float*)d_in[18]; ws.p[7] = (const float*)d_in[20];
    ws.p[8] = (const float*)d_in[26];
    wprep_all<<<(663552 + 255) / 256, 256>>>(ws, whi, wlo);
    dcnprep_all<<<dim3(176, 2), 256>>>(dcn1_w, dcn2_w, dwhi, dwlo);
    tohwc_kernel<<<512, 128>>>(feat_prev, xt);

    dim3 g1(256, 1), g4(256, 4), mg(4, 256);

    // branch prev
    gconv_kernel<2,0,0><<<g1, 256, GSM>>>(extra_feat_prev, nullptr, nullptr, whi + 0, wlo + 0,
        o1b[0], 64, 64, nullptr, nullptr, nullptr, ahiA, aloA);
    gconv_kernel<1,0,1><<<g1, 256, GSM>>>(nullptr, ahiA, aloA, whi + 73728, wlo + 73728,
        o1b[1], 64, 64, nullptr, nullptr, nullptr, ahiB, aloB);
    gconv_kernel<1,0,1><<<g1, 256, GSM>>>(nullptr, ahiB, aloB, whi + 110592, wlo + 110592,
        o1b[2], 64, 64, nullptr, nullptr, nullptr, ahiA, aloA);
    gconv_kernel<1,2,1><<<g4, 256, GSM>>>(nullptr, ahiA, aloA, whi + 147456, wlo + 147456,
        o1b[3], 216, 256, offp, maskp, flow_prev, nullptr, nullptr);
    mdcn_kernel<<<mg, 256>>>(xt, offp, maskp, dwhi, dwlo, dcn1_b, catp);

    // branch next
    gconv_kernel<2,0,0><<<g1, 256, GSM>>>(extra_feat_next, nullptr, nullptr, whi + 294912, wlo + 294912,
        o2b[0], 64, 64, nullptr, nullptr, nullptr, ahiA, aloA);
    gconv_kernel<1,0,1><<<g1, 256, GSM>>>(nullptr, ahiA, aloA, whi + 368640, wlo + 368640,
        o2b[1], 64, 64, nullptr, nullptr, nullptr, ahiB, aloB);
    gconv_kernel<1,0,1><<<g1, 256, GSM>>>(nullptr, ahiB, aloB, whi + 405504, wlo + 405504,
        o2b[2], 64, 64, nullptr, nullptr, nullptr, ahiA, aloA);
    gconv_kernel<1,2,1><<<g4, 256, GSM>>>(nullptr, ahiA, aloA, whi + 442368, wlo + 442368,
        o2b[3], 216, 256, offp, maskp, flow_next, nullptr, nullptr);
    tohwc_kernel<<<512, 128>>>(feat_next, xt);
    mdcn_kernel<<<mg, 256>>>(xt, offp, maskp, dwhi + 45056, dwlo + 45056, dcn2_b, catp + (size_t)64 * HW);

    // fusion
    gconv_kernel<2,1,0><<<g1, 256, GSM>>>(catp, nullptr, nullptr, whi + 589824, wlo + 589824,
        fus_b, 64, 64, out, nullptr, nullptr, nullptr, nullptr);
}

// round 15
// speedup vs baseline: 5.4139x; 1.0174x over previous
#include <cuda_runtime.h>
#include <cuda_fp16.h>
#include <math.h>

#define Wd 256
#define Hd 256
#define HW 65536
typedef unsigned int u32;

// ---------------- scratch (no allocation allowed) ----------------
__device__ float g_off [2 * 144 * HW];
__device__ float g_mask[2 * 72 * HW];
__device__ float g_cat [128 * HW];
__device__ __align__(16) __half g_xt[2 * 64 * HW];           // NHWC feat per branch
__device__ __align__(16) __half g_act_hi[4 * HW * 64];       // [pp*2+branch]
__device__ __align__(16) __half g_act_lo[4 * HW * 64];
__device__ __align__(16) __half g_whi[663552];
__device__ __align__(16) __half g_wlo[663552];
__device__ __align__(16) __half g_dwhi[2 * 45056];
__device__ __align__(16) __half g_dwlo[2 * 45056];

// ---------------- merged conv-weight pre-convert ----------------
struct WSrc { const float* p[9]; };
__global__ void wprep_all(WSrc ws, __half* __restrict__ dhi, __half* __restrict__ dlo)
{
    const int off[9]  = {0,73728,110592,147456,294912,368640,405504,442368,589824};
    const int CINs[9] = {128,64,64,64,128,64,64,64,128};
    const int OCs[9]  = {64,64,64,216,64,64,64,216,64};
    const int OCp[9]  = {64,64,64,256,64,64,64,256,64};
    int idx = blockIdx.x * 256 + threadIdx.x;
    if (idx >= 663552) return;
    int seg = 0;
#pragma unroll
    for (int s = 1; s < 9; s++) if (idx >= off[s]) seg = s;
    int r = idx - off[seg];
    int per_t = OCp[seg] * CINs[seg];
    int t = r / per_t; r -= t * per_t;
    int o = r / CINs[seg], c = r - o * CINs[seg];
    float w = (o < OCs[seg]) ? ws.p[seg][(o * CINs[seg] + c) * 9 + t] : 0.f;
    __half h = __float2half_rn(w);
    dhi[idx] = h;
    dlo[idx] = __float2half_rn(w - __half2float(h));
}

// ---------------- dcn weight pre-convert ----------------
__global__ void dcnprep_all(const float* __restrict__ s1, const float* __restrict__ s2,
                            __half* __restrict__ dhi, __half* __restrict__ dlo)
{
    int idx = blockIdx.x * 256 + threadIdx.x;
    if (idx >= 45056) return;
    const float* src = blockIdx.y ? s2 : s1;
    int base = blockIdx.y * 45056;
    int g = idx / 5632, r = idx - g * 5632, o = r / 88, ck = r - o * 88;
    float w = 0.f;
    if (ck < 72) { int c = ck / 9, k = ck - c * 9; w = src[((size_t)o * 64 + g * 8 + c) * 9 + k]; }
    __half h = __float2half_rn(w);
    dhi[base + idx] = h;
    dlo[base + idx] = __float2half_rn(w - __half2float(h));
}

// ---------------- NCHW fp32 -> NHWC fp16 (both feats) ----------------
__global__ __launch_bounds__(128)
void tohwc_kernel(const float* __restrict__ s0, const float* __restrict__ s1,
                  __half* __restrict__ dst)
{
    __shared__ float s[64 * 130];
    const int t = threadIdx.x;
    const int pix0 = blockIdx.x * 128;
    const float* src = blockIdx.y ? s1 : s0;
    dst += (size_t)blockIdx.y * 64 * HW;
    for (int c = 0; c < 64; c++) s[c * 130 + t] = src[(size_t)c * HW + pix0 + t];
    __syncthreads();
    for (int i = 0; i < 64; i++) {
        int L = t + i * 128;
        dst[(size_t)pix0 * 64 + L] = __float2half_rn(s[(L & 63) * 130 + (L >> 6)]);
    }
}

__device__ __forceinline__ void mma16816(float* d, const u32* a, u32 b0, u32 b1) {
    asm volatile(
        "mma.sync.aligned.m16n8k16.row.col.f32.f16.f16.f32 "
        "{%0,%1,%2,%3}, {%4,%5,%6,%7}, {%8,%9}, {%0,%1,%2,%3};"
        : "+f"(d[0]), "+f"(d[1]), "+f"(d[2]), "+f"(d[3])
        : "r"(a[0]), "r"(a[1]), "r"(a[2]), "r"(a[3]), "r"(b0), "r"(b1));
}
__device__ __forceinline__ void ldsm4(u32* r, u32 addr) {
    asm volatile("ldmatrix.sync.aligned.m8n8.x4.shared.b16 {%0,%1,%2,%3}, [%4];"
                 : "=r"(r[0]), "=r"(r[1]), "=r"(r[2]), "=r"(r[3]) : "r"(addr));
}
__device__ __forceinline__ u32 smem_u32(const void* p) {
    return (u32)__cvta_generic_to_shared(p);
}
__device__ __forceinline__ void cp_async16(void* dst, const void* src, int sb) {
    asm volatile("cp.async.cg.shared.global [%0], [%1], 16, %2;\n"
                 :: "r"(smem_u32(dst)), "l"(src), "r"(sb) : "memory");
}
__device__ __forceinline__ void cp_commit() {
    asm volatile("cp.async.commit_group;\n" ::: "memory");
}
template<int N>
__device__ __forceinline__ void cp_wait() {
    asm volatile("cp.async.wait_group %0;\n" :: "n"(N) : "memory");
}

// per-branch pointer bundle
struct BP {
    const float* in;
    const __half* inhi; const __half* inlo;
    const float* bias;
    float* outf; float* outf2;
    const float* flow;
    __half* outhi; __half* outlo;
};

// ---------------- HMMA implicit-GEMM 3x3 conv (branch-merged) ----------------
#define GSM 75264
template<int NCB, int MODE, int INFMT>
__global__ __launch_bounds__(256)
void gconv_kernel(BP b0, BP b1, const __half* __restrict__ whi_,
                  const __half* __restrict__ wlo_, int wdelta,
                  int oc_total, int OCpad)
{
    extern __shared__ char smem_[];
    __half* sAhi = (__half*)smem_;
    __half* sAlo = (__half*)(smem_ + 27200);
    __half* sWb  = (__half*)(smem_ + 54400);
    float* sbias = (float*)(smem_ + 74880);

    const int br = blockIdx.z;
    const BP b = br ? b1 : b0;
    const __half* whi = whi_ + br * wdelta;
    const __half* wlo = wlo_ + br * wdelta;

    const int tid = threadIdx.x;
    const int wid = tid >> 5, lane = tid & 31;
    const int h0 = (blockIdx.x >> 3) * 8;
    const int w00 = (blockIdx.x & 7) * 32;
    const int ocb = blockIdx.y * 64;
    const int CIN = NCB * 64;
    int nfb = (oc_total - ocb + 7) >> 3; if (nfb > 8) nfb = 8;

    const u32 sAhi_a = smem_u32(sAhi), sAlo_a = smem_u32(sAlo);
    const u32 sW_a   = smem_u32(sWb);

    if (tid < 64) sbias[tid] = (ocb + tid < oc_total) ? b.bias[ocb + tid] : 0.f;

    const int wo = tid >> 2, wq = (tid & 3) * 8;

    float acc0[8][4], acc1[8][4];
#pragma unroll
    for (int i = 0; i < 8; i++)
#pragma unroll
        for (int j = 0; j < 4; j++) { acc0[i][j] = 0.f; acc1[i][j] = 0.f; }

    const int a_dp = (lane & 7) + ((lane >> 3) & 1) * 8;
    const int a_dc = (lane >> 4) * 8;
    const int b_dn = (lane & 7) + ((lane >> 4) & 1) * 8;
    const int b_dc = ((lane >> 3) & 1) * 8;

    for (int cb = 0; cb < NCB; cb++)
    for (int hf = 0; hf < 2; hf++) {
        const int c0 = cb * 64 + hf * 32;
        __syncthreads();
        if (INFMT == 0) {
#pragma unroll
            for (int i = 0; i < 5; i++) {
                int j = tid + i * 256;
                int rr = j >> 7, rem = j & 127;
                int cp = rem >> 3, q = rem & 7;
                int gh = h0 - 1 + rr;
                int c = cp * 2;
                float4 va = make_float4(0.f, 0.f, 0.f, 0.f), vb = va;
                if ((unsigned)gh < Hd) {
                    const float* p = b.in + (size_t)(c0 + c) * HW + gh * Wd + (w00 + q * 4);
                    va = *(const float4*)p;
                    vb = *(const float4*)(p + HW);
                }
                float av[4] = {va.x, va.y, va.z, va.w};
                float bv[4] = {vb.x, vb.y, vb.z, vb.w};
                int ptb = rr * 34 + 1 + q * 4;
#pragma unroll
                for (int k = 0; k < 4; k++) {
                    __half ha = __float2half_rn(av[k]), hb = __float2half_rn(bv[k]);
                    __half la = __float2half_rn(av[k] - __half2float(ha));
                    __half lb = __float2half_rn(bv[k] - __half2float(hb));
                    *(__half2*)&sAhi[(ptb + k) * 40 + c] = __halves2half2(ha, hb);
                    *(__half2*)&sAlo[(ptb + k) * 40 + c] = __halves2half2(la, lb);
                }
            }
#pragma unroll
            for (int i = 0; i < 2; i++) {
                int j = tid + i * 256;
                if (j < 320) {
                    int rr = j >> 5, rem = j & 31;
                    int cp = rem >> 1, e = rem & 1;
                    int s = e ? 33 : 0;
                    int gh = h0 - 1 + rr, gw = w00 - 1 + s;
                    int c = cp * 2;
                    float v0 = 0.f, v1 = 0.f;
                    if ((unsigned)gh < Hd && (unsigned)gw < Wd) {
                        const float* p = b.in + (size_t)(c0 + c) * HW + gh * Wd + gw;
                        v0 = p[0]; v1 = p[HW];
                    }
                    __half h0v = __float2half_rn(v0), h1v = __float2half_rn(v1);
                    __half l0v = __float2half_rn(v0 - __half2float(h0v));
                    __half l1v = __float2half_rn(v1 - __half2float(h1v));
                    int pt = rr * 34 + s;
                    *(__half2*)&sAhi[pt * 40 + c] = __halves2half2(h0v, h1v);
                    *(__half2*)&sAlo[pt * 40 + c] = __halves2half2(l0v, l1v);
                }
            }
        } else {
#pragma unroll
            for (int i = 0; i < 11; i++) {
                int j = tid + i * 256;
                if (j < 2720) {
                    int plane = (j >= 1360) ? 1 : 0;
                    int jj = j - plane * 1360;
                    int p = jj >> 2, q = jj & 3;
                    int rr = p / 34, s = p - rr * 34;
                    int gh = h0 - 1 + rr, gw = w00 - 1 + s;
                    bool v = ((unsigned)gh < Hd) && ((unsigned)gw < Wd);
                    const __half* base = plane ? b.inlo : b.inhi;
                    const __half* src = v ? (base + ((size_t)(gh * Wd + gw)) * 64 + c0 + q * 8)
                                          : base;
                    __half* dst = (plane ? sAlo : sAhi) + p * 40 + q * 8;
                    cp_async16(dst, src, v ? 16 : 0);
                }
            }
            cp_commit();
            cp_wait<0>();
        }
        {
            size_t gi = (size_t)(0 * OCpad + ocb + wo) * CIN + c0 + wq;
            *(uint4*)&sWb[0 * 2560 + wo * 40 + wq]        = *(const uint4*)&whi[gi];
            *(uint4*)&sWb[5120 + 0 * 2560 + wo * 40 + wq] = *(const uint4*)&wlo[gi];
        }

        for (int tap = 0; tap < 9; tap++) {
            __syncthreads();
            const int buf = tap & 1;
            if (tap < 8) {
                const int nb = (tap + 1) & 1;
                size_t gi = (size_t)((tap + 1) * OCpad + ocb + wo) * CIN + c0 + wq;
                *(uint4*)&sWb[nb * 2560 + wo * 40 + wq]        = *(const uint4*)&whi[gi];
                *(uint4*)&sWb[5120 + nb * 2560 + wo * 40 + wq] = *(const uint4*)&wlo[gi];
            }
            const u32 whi_a = sW_a + buf * 5120;
            const u32 wlo_a = whi_a + 10240;
            const int pb0 = (tap / 3 + wid) * 34 + (tap % 3);
#pragma unroll
            for (int ks = 0; ks < 2; ks++) {
                const int kc = ks * 16;
                const int ch = kc + a_dc;
                u32 ah0[4], al0[4], ah1[4], al1[4];
                ldsm4(ah0, sAhi_a + ((pb0 + a_dp) * 40 + ch) * 2);
                ldsm4(al0, sAlo_a + ((pb0 + a_dp) * 40 + ch) * 2);
                ldsm4(ah1, sAhi_a + ((pb0 + 16 + a_dp) * 40 + ch) * 2);
                ldsm4(al1, sAlo_a + ((pb0 + 16 + a_dp) * 40 + ch) * 2);
#pragma unroll
                for (int pr = 0; pr < 4; pr++) {
                    if (pr * 2 < nfb) {
                        const int n = pr * 16 + b_dn;
                        const u32 wo32 = (n * 40 + kc + b_dc) * 2;
                        u32 bh[4], bl[4];
                        ldsm4(bh, whi_a + wo32);
                        ldsm4(bl, wlo_a + wo32);
                        const int nf = pr * 2;
                        mma16816(acc0[nf], ah0, bh[0], bh[1]);
                        mma16816(acc0[nf], al0, bh[0], bh[1]);
                        mma16816(acc0[nf], ah0, bl[0], bl[1]);
                        mma16816(acc1[nf], ah1, bh[0], bh[1]);
                        mma16816(acc1[nf], al1, bh[0], bh[1]);
                        mma16816(acc1[nf], ah1, bl[0], bl[1]);
                        if (nf + 1 < nfb) {
                            mma16816(acc0[nf+1], ah0, bh[2], bh[3]);
                            mma16816(acc0[nf+1], al0, bh[2], bh[3]);
                            mma16816(acc0[nf+1], ah0, bl[2], bl[3]);
                            mma16816(acc1[nf+1], ah1, bh[2], bh[3]);
                            mma16816(acc1[nf+1], al1, bh[2], bh[3]);
                            mma16816(acc1[nf+1], ah1, bl[2], bl[3]);
                        }
                    }
                }
            }
        }
    }

    const int row = h0 + wid;
    const int pcol = w00 + (lane >> 2);
    const int ocl = (lane & 3) * 2;
#pragma unroll
    for (int nf = 0; nf < 8; nf++) {
        if (nf >= nfb) break;
        const int oc = ocb + nf * 8 + ocl;
        const float bb0 = sbias[nf * 8 + ocl], bb1 = sbias[nf * 8 + ocl + 1];
#pragma unroll
        for (int sl = 0; sl < 2; sl++) {
            const float* a = sl ? acc1[nf] : acc0[nf];
#pragma unroll
            for (int half_ = 0; half_ < 2; half_++) {
                const int px = row * Wd + pcol + sl * 16 + half_ * 8;
                float r0 = a[half_ * 2 + 0] + bb0;
                float r1 = a[half_ * 2 + 1] + bb1;
                if (MODE == 0) {
                    r0 = (r0 >= 0.f) ? r0 : 0.1f * r0;
                    r1 = (r1 >= 0.f) ? r1 : 0.1f * r1;
                    __half h0v = __float2half_rn(r0), h1v = __float2half_rn(r1);
                    __half l0v = __float2half_rn(r0 - __half2float(h0v));
                    __half l1v = __float2half_rn(r1 - __half2float(h1v));
                    *(__half2*)&b.outhi[(size_t)px * 64 + oc] = __halves2half2(h0v, h1v);
                    *(__half2*)&b.outlo[(size_t)px * 64 + oc] = __halves2half2(l0v, l1v);
                } else if (MODE == 1) {
                    b.outf[(size_t)oc * HW + px] = r0;
                    b.outf[(size_t)(oc + 1) * HW + px] = r1;
                } else {
                    float rr[2] = {r0, r1};
#pragma unroll
                    for (int t = 0; t < 2; t++) {
                        const int o2 = oc + t;
                        if (o2 < 144) {
                            b.outf[(size_t)o2 * HW + px] =
                                10.0f * tanhf(rr[t]) + b.flow[((size_t)((o2 & 1) ^ 1)) * HW + px];
                        } else if (o2 < 216) {
                            b.outf2[(size_t)(o2 - 144) * HW + px] = 1.0f / (1.0f + expf(-rr[t]));
                        }
                    }
                }
            }
        }
    }
}

// ---------------- mdcn (branch-merged) ----------------
__global__ __launch_bounds__(256)
void mdcn_kernel(const __half* __restrict__ xt, const float* __restrict__ off,
                 const float* __restrict__ mask, const __half* __restrict__ dwhi,
                 const __half* __restrict__ dwlo, const float* __restrict__ bias0,
                 const float* __restrict__ bias1, float* __restrict__ out)
{
    __shared__ __align__(16) __half sShi[64 * 90], sSlo[64 * 90];
    __shared__ __align__(16) __half sWhi[64 * 88], sWlo[64 * 88];
    __shared__ float sbias[64];
    const int br = blockIdx.z;
    xt   += (size_t)br * 64 * HW;
    off  += (size_t)br * 144 * HW;
    mask += (size_t)br * 72 * HW;
    dwhi += br * 45056;
    dwlo += br * 45056;
    out  += (size_t)br * 64 * HW;
    const float* bias = br ? bias1 : bias0;

    const int tid = threadIdx.x;
    const int wid = tid >> 5, lane = tid & 31;
    const int h = blockIdx.y;
    const int col0 = blockIdx.x * 64;
    const int px = tid & 63;
    const int part = tid >> 6;
    const int pixg = col0 + px;
    const int hw = h * Wd + pixg;
    const int k_beg = (part == 0) ? 0 : 1 + part * 2;
    const int k_end = (part == 0) ? 3 : 3 + part * 2;

    if (tid < 64) sbias[tid] = bias[tid];
    for (int i = tid; i < 64 * 8; i += 256) {
        int p = i >> 3, j = i & 7;
        sShi[p * 90 + 72 + j] = __ushort_as_half(0);
        sSlo[p * 90 + 72 + j] = __ushort_as_half(0);
    }

    float acc[8][4];
#pragma unroll
    for (int i = 0; i < 8; i++)
#pragma unroll
        for (int j = 0; j < 4; j++) acc[i][j] = 0.f;

    for (int g = 0; g < 8; g++) {
        __syncthreads();
        {
            const u32* gh32 = (const u32*)(dwhi + g * 5632);
            const u32* gl32 = (const u32*)(dwlo + g * 5632);
            for (int i = tid; i < 2816; i += 256) {
                ((u32*)sWhi)[i] = gh32[i];
                ((u32*)sWlo)[i] = gl32[i];
            }
        }
        for (int k = k_beg; k < k_end; k++) {
            int gk = g * 9 + k;
            float offy = off[(gk * 2 + 0) * HW + hw];
            float offx = off[(gk * 2 + 1) * HW + hw];
            float m    = mask[gk * HW + hw];
            float py = (float)h    + (float)(k / 3 - 1) + offy;
            float pxf = (float)pixg + (float)(k % 3 - 1) + offx;
            float y0f = floorf(py), x0f = floorf(pxf);
            float ly = py - y0f, lx = pxf - x0f;
            int y0 = (int)y0f, x0i = (int)x0f;
            int y1 = y0 + 1,  x1 = x0i + 1;
            bool vy0 = (unsigned)y0 < Hd, vy1 = (unsigned)y1 < Hd;
            bool vx0 = (unsigned)x0i < Wd, vx1 = (unsigned)x1 < Wd;
            int yc0 = min(max(y0, 0), Hd - 1), yc1 = min(max(y1, 0), Hd - 1);
            int xc0 = min(max(x0i, 0), Wd - 1), xc1 = min(max(x1, 0), Wd - 1);
            float w00 = (vy0 && vx0) ? (1.f - ly) * (1.f - lx) * m : 0.f;
            float w01 = (vy0 && vx1) ? (1.f - ly) * lx * m : 0.f;
            float w10 = (vy1 && vx0) ? ly * (1.f - lx) * m : 0.f;
            float w11 = (vy1 && vx1) ? ly * lx * m : 0.f;
            uint4 r00 = *(const uint4*)(xt + ((size_t)(yc0 * Wd + xc0)) * 64 + g * 8);
            uint4 r01 = *(const uint4*)(xt + ((size_t)(yc0 * Wd + xc1)) * 64 + g * 8);
            uint4 r10 = *(const uint4*)(xt + ((size_t)(yc1 * Wd + xc0)) * 64 + g * 8);
            uint4 r11 = *(const uint4*)(xt + ((size_t)(yc1 * Wd + xc1)) * 64 + g * 8);
            const __half2* hA = (const __half2*)&r00;
            const __half2* hB = (const __half2*)&r01;
            const __half2* hC = (const __half2*)&r10;
            const __half2* hD = (const __half2*)&r11;
#pragma unroll
            for (int cc = 0; cc < 4; cc++) {
                float2 fa = __half22float2(hA[cc]);
                float2 fb = __half22float2(hB[cc]);
                float2 fc = __half22float2(hC[cc]);
                float2 fd = __half22float2(hD[cc]);
                float s0 = w00 * fa.x + w01 * fb.x + w10 * fc.x + w11 * fd.x;
                float s1 = w00 * fa.y + w01 * fb.y + w10 * fc.y + w11 * fd.y;
                __half h0 = __float2half_rn(s0), h1 = __float2half_rn(s1);
                sShi[px * 90 + (cc * 2 + 0) * 9 + k] = h0;
                sShi[px * 90 + (cc * 2 + 1) * 9 + k] = h1;
                sSlo[px * 90 + (cc * 2 + 0) * 9 + k] = __float2half_rn(s0 - __half2float(h0));
                sSlo[px * 90 + (cc * 2 + 1) * 9 + k] = __float2half_rn(s1 - __half2float(h1));
            }
        }
        __syncthreads();
        const int mw = wid & 3;
        const int nhalf = (wid >> 2) * 4;
        const int r = mw * 16 + (lane >> 2);
#pragma unroll
        for (int ks = 0; ks < 5; ks++) {
            const int kc = ks * 16 + (lane & 3) * 2;
            u32 ah[4], al[4];
            ah[0] = *(const u32*)&sShi[r * 90 + kc];
            ah[1] = *(const u32*)&sShi[(r + 8) * 90 + kc];
            ah[2] = *(const u32*)&sShi[r * 90 + kc + 8];
            ah[3] = *(const u32*)&sShi[(r + 8) * 90 + kc + 8];
            al[0] = *(const u32*)&sSlo[r * 90 + kc];
            al[1] = *(const u32*)&sSlo[(r + 8) * 90 + kc];
            al[2] = *(const u32*)&sSlo[r * 90 + kc + 8];
            al[3] = *(const u32*)&sSlo[(r + 8) * 90 + kc + 8];
#pragma unroll
            for (int nf = 0; nf < 4; nf++) {
                const int n = (nhalf + nf) * 8 + (lane >> 2);
                u32 bh0 = *(const u32*)&sWhi[n * 88 + kc];
                u32 bh1 = *(const u32*)&sWhi[n * 88 + kc + 8];
                u32 bl0 = *(const u32*)&sWlo[n * 88 + kc];
                u32 bl1 = *(const u32*)&sWlo[n * 88 + kc + 8];
                mma16816(acc[nf], ah, bh0, bh1);
                mma16816(acc[nf], al, bh0, bh1);
                mma16816(acc[nf], ah, bl0, bl1);
            }
        }
    }
    const int mw = wid & 3, nhalf = (wid >> 2) * 4;
    const int p1 = col0 + mw * 16 + (lane >> 2);
    const int p2 = p1 + 8;
    const int oc0 = (lane & 3) * 2;
#pragma unroll
    for (int nf = 0; nf < 4; nf++) {
        const int oc = (nhalf + nf) * 8 + oc0;
        out[(size_t)oc * HW + h * Wd + p1]       = acc[nf][0] + sbias[oc];
        out[(size_t)(oc + 1) * HW + h * Wd + p1] = acc[nf][1] + sbias[oc + 1];
        out[(size_t)oc * HW + h * Wd + p2]       = acc[nf][2] + sbias[oc];
        out[(size_t)(oc + 1) * HW + h * Wd + p2] = acc[nf][3] + sbias[oc + 1];
    }
}

// ---------------- host orchestration ----------------
extern "C" void kernel_launch(void* const* d_in, const int* in_sizes, int n_in,
                              void* d_out, int out_size)
{
    const float* feat_prev       = (const float*)d_in[0];
    const float* feat_next       = (const float*)d_in[1];
    const float* extra_feat_prev = (const float*)d_in[2];
    const float* extra_feat_next = (const float*)d_in[3];
    const float* flow_prev       = (const float*)d_in[4];
    const float* flow_next       = (const float*)d_in[5];
    const float* o1b[4] = {(const float*)d_in[7],  (const float*)d_in[9],
                           (const float*)d_in[11], (const float*)d_in[13]};
    const float* o2b[4] = {(const float*)d_in[15], (const float*)d_in[17],
                           (const float*)d_in[19], (const float*)d_in[21]};
    const float* dcn1_w = (const float*)d_in[22];
    const float* dcn1_b = (const float*)d_in[23];
    const float* dcn2_w = (const float*)d_in[24];
    const float* dcn2_b = (const float*)d_in[25];
    const float* fus_b  = (const float*)d_in[27];
    float* out = (float*)d_out;

    float *offp, *maskp, *catp;
    __half *xt, *whi, *wlo, *dwhi, *dwlo, *ahi, *alo;
    cudaGetSymbolAddress((void**)&offp,  g_off);
    cudaGetSymbolAddress((void**)&maskp, g_mask);
    cudaGetSymbolAddress((void**)&catp,  g_cat);
    cudaGetSymbolAddress((void**)&xt,    g_xt);
    cudaGetSymbolAddress((void**)&whi, g_whi);
    cudaGetSymbolAddress((void**)&wlo, g_wlo);
    cudaGetSymbolAddress((void**)&dwhi, g_dwhi);
    cudaGetSymbolAddress((void**)&dwlo, g_dwlo);
    cudaGetSymbolAddress((void**)&ahi, g_act_hi);
    cudaGetSymbolAddress((void**)&alo, g_act_lo);

    cudaFuncSetAttribute(gconv_kernel<2,0,0>, cudaFuncAttributeMaxDynamicSharedMemorySize, GSM);
    cudaFuncSetAttribute(gconv_kernel<1,0,1>, cudaFuncAttributeMaxDynamicSharedMemorySize, GSM);
    cudaFuncSetAttribute(gconv_kernel<1,2,1>, cudaFuncAttributeMaxDynamicSharedMemorySize, GSM);
    cudaFuncSetAttribute(gconv_kernel<2,1,0>, cudaFuncAttributeMaxDynamicSharedMemorySize, GSM);

    WSrc ws;
    ws.p[0] = (const float*)d_in[6];  ws.p[1] = (const float*)d_in[8];
    ws.p[2] = (const float*)d_in[10]; ws.p[3] = (const float*)d_in[12];
    ws.p[4] = (const float*)d_in[14]; ws.p[5] = (const float*)d_in[16];
    ws.p[6] = (const float*)d_in[18]; ws.p[7] = (const float*)d_in[20];
    ws.p[8] = (const float*)d_in[26];
    wprep_all<<<(663552 + 255) / 256, 256>>>(ws, whi, wlo);
    dcnprep_all<<<dim3(176, 2), 256>>>(dcn1_w, dcn2_w, dwhi, dwlo);
    tohwc_kernel<<<dim3(512, 2), 128>>>(feat_prev, feat_next, xt);

    const size_t S = (size_t)HW * 64;
    // activation slots: [pp*2 + branch]
    auto mkBP = [&](int branch, const float* in, const __half* ihi, const __half* ilo,
                    const float* bias, float* outf, float* outf2, const float* flow,
                    __half* ohi, __half* olo) {
        BP b; b.in = in; b.inhi = ihi; b.inlo = ilo; b.bias = bias;
        b.outf = outf; b.outf2 = outf2; b.flow = flow; b.outhi = ohi; b.outlo = olo;
        return b;
    };
    __half *hi00 = ahi + 0 * S, *lo00 = alo + 0 * S;   // pp0 br0
    __half *hi01 = ahi + 1 * S, *lo01 = alo + 1 * S;   // pp0 br1
    __half *hi10 = ahi + 2 * S, *lo10 = alo + 2 * S;   // pp1 br0
    __half *hi11 = ahi + 3 * S, *lo11 = alo + 3 * S;   // pp1 br1

    dim3 g2(256, 1, 2), g42(256, 4, 2), mg2(4, 256, 2), gf(256, 1, 1);

    // L1: extra -> pp0
    gconv_kernel<2,0,0><<<g2, 256, GSM>>>(
        mkBP(0, extra_feat_prev, nullptr, nullptr, o1b[0], nullptr, nullptr, nullptr, hi00, lo00),
        mkBP(1, extra_feat_next, nullptr, nullptr, o2b[0], nullptr, nullptr, nullptr, hi01, lo01),
        whi, wlo, 294912, 64, 64);
    // L2: pp0 -> pp1
    gconv_kernel<1,0,1><<<g2, 256, GSM>>>(
        mkBP(0, nullptr, hi00, lo00, o1b[1], nullptr, nullptr, nullptr, hi10, lo10),
        mkBP(1, nullptr, hi01, lo01, o2b[1], nullptr, nullptr, nullptr, hi11, lo11),
        whi + 73728, wlo + 73728, 294912, 64, 64);
    // L3: pp1 -> pp0
    gconv_kernel<1,0,1><<<g2, 256, GSM>>>(
        mkBP(0, nullptr, hi10, lo10, o1b[2], nullptr, nullptr, nullptr, hi00, lo00),
        mkBP(1, nullptr, hi11, lo11, o2b[2], nullptr, nullptr, nullptr, hi01, lo01),
        whi + 110592, wlo + 110592, 294912, 64, 64);
    // L4: pp0 -> off/mask (per-branch regions)
    gconv_kernel<1,2,1><<<g42, 256, GSM>>>(
        mkBP(0, nullptr, hi00, lo00, o1b[3], offp, maskp, flow_prev, nullptr, nullptr),
        mkBP(1, nullptr, hi01, lo01, o2b[3], offp + (size_t)144 * HW, maskp + (size_t)72 * HW,
             flow_next, nullptr, nullptr),
        whi + 147456, wlo + 147456, 294912, 216, 256);
    // mdcn both branches
    mdcn_kernel<<<mg2, 256>>>(xt, offp, maskp, dwhi, dwlo, dcn1_b, dcn2_b, catp);
    // fusion
    gconv_kernel<2,1,0><<<gf, 256, GSM>>>(
        mkBP(0, catp, nullptr, nullptr, fus_b, out, nullptr, nullptr, nullptr, nullptr),
        mkBP(0, catp, nullptr, nullptr, fus_b, out, nullptr, nullptr, nullptr, nullptr),
        whi + 589824, wlo + 589824, 0, 64, 64);
}